// round 11
// baseline (speedup 1.0000x reference)
#include <cuda_runtime.h>
#include <cuda_bf16.h>
#include <math.h>
#include <cstdint>

#define NFEAT   256
#define HIDDEN  256
#define PCH     64
#define NCLASS  4
#define MAXN    100000
#define MAXE    1600000

typedef unsigned long long ull;

__device__ __forceinline__ ull pack2(float x, float y) {
    ull r; asm("mov.b64 %0, {%1,%2};" : "=l"(r) : "f"(x), "f"(y)); return r;
}
__device__ __forceinline__ void unpack2(ull v, float& x, float& y) {
    asm("mov.b64 {%0,%1}, %2;" : "=f"(x), "=f"(y) : "l"(v));
}
__device__ __forceinline__ void ffma2(ull& d, ull a, ull b) {
    asm("fma.rn.f32x2 %0, %1, %2, %0;" : "+l"(d) : "l"(a), "l"(b));
}
__device__ __forceinline__ uint32_t smem_u32(const void* p) {
    uint32_t a;
    asm("{ .reg .u64 t; cvta.to.shared.u64 t, %1; cvt.u32.u64 %0, t; }"
        : "=r"(a) : "l"(p));
    return a;
}
__device__ __forceinline__ void ldsm4(uint32_t addr, uint32_t& r0, uint32_t& r1,
                                      uint32_t& r2, uint32_t& r3) {
    asm volatile("ldmatrix.sync.aligned.m8n8.x4.shared.b16 {%0,%1,%2,%3}, [%4];"
                 : "=r"(r0), "=r"(r1), "=r"(r2), "=r"(r3) : "r"(addr));
}
__device__ __forceinline__ void mma16816(float* c, uint32_t a0, uint32_t a1,
                                         uint32_t a2, uint32_t a3,
                                         uint32_t b0, uint32_t b1) {
    asm volatile(
        "mma.sync.aligned.m16n8k16.row.col.f32.bf16.bf16.f32 "
        "{%0,%1,%2,%3}, {%4,%5,%6,%7}, {%8,%9}, {%0,%1,%2,%3};"
        : "+f"(c[0]), "+f"(c[1]), "+f"(c[2]), "+f"(c[3])
        : "r"(a0), "r"(a1), "r"(a2), "r"(a3), "r"(b0), "r"(b1));
}
__device__ __forceinline__ void cp16z(uint32_t dst, const void* src, int inb) {
    int sz = inb ? 16 : 0;
    asm volatile("cp.async.cg.shared.global [%0], [%1], 16, %2;"
                 :: "r"(dst), "l"(src), "r"(sz));
}
__device__ __forceinline__ void cp16(uint32_t dst, const void* src) {
    asm volatile("cp.async.cg.shared.global [%0], [%1], 16;"
                 :: "r"(dst), "l"(src));
}

// ---------------- device scratch ----------------
__device__ int   g_is64;
__device__ float g_cb[HIDDEN];
__device__ float g_proj[MAXN * 8];
__device__ float g_c[(size_t)MAXN * HIDDEN];
__device__ __nv_bfloat16 g_xhi[(size_t)MAXN * NFEAT];
__device__ __nv_bfloat16 g_xlo[(size_t)MAXN * NFEAT];
__device__ __nv_bfloat16 g_cwhi[HIDDEN * NFEAT];
__device__ __nv_bfloat16 g_cwlo[HIDDEN * NFEAT];
__device__ int   g_counts[MAXN];
__device__ int   g_rowstart[MAXN];
__device__ int   g_cursor[MAXN];
__device__ int   g_csrcol[MAXE];
__device__ int   g_bsum[512];
__device__ int   g_boff[512];

// ---------------- index width sniffing ----------------
__global__ void k_detect(const unsigned int* __restrict__ rowp, int E) {
    if (threadIdx.x == 0 && blockIdx.x == 0) {
        int n = E < 64 ? E : 64;
        int all_hi_zero = 1;
        for (int i = 0; i < n; i++)
            if (rowp[2 * i + 1] != 0u) { all_hi_zero = 0; break; }
        g_is64 = all_hi_zero;
    }
}

// ---------------- fold conv into lin, output bf16 hi/lo ----------------
__global__ void k_fold(const float* __restrict__ conv_W,
                       const float* __restrict__ lin_W,
                       const float* __restrict__ lin_b) {
    int t = blockIdx.x, f = threadIdx.x;
    int k = t >> 6, q = t & 63;
    const float* cw = conv_W + (k * PCH + q) * PCH;
    const float* lw = lin_W + (size_t)k * PCH * NFEAT;
    float s = 0.f;
    #pragma unroll 8
    for (int p = 0; p < PCH; p++) s = fmaf(cw[p], lw[p * NFEAT + f], s);
    __nv_bfloat16 hi = __float2bfloat16(s);
    g_cwhi[t * NFEAT + f] = hi;
    g_cwlo[t * NFEAT + f] = __float2bfloat16(s - __bfloat162float(hi));
    if (f == 0) {
        const float* lb = lin_b + k * PCH;
        float b = 0.f;
        for (int p = 0; p < PCH; p++) b = fmaf(cw[p], lb[p], b);
        g_cb[t] = b;
    }
}

// ---------------- projections + x split (single x read) ----------------
__global__ void k_proj(const float* __restrict__ x,
                       const float* __restrict__ asg_W1, int N) {
    int warp = (blockIdx.x * blockDim.x + threadIdx.x) >> 5;
    int lane = threadIdx.x & 31;
    if (warp >= N) return;
    const float* xr = x + (size_t)warp * NFEAT;
    float pa[4] = {0,0,0,0}, pb[4] = {0,0,0,0};
    #pragma unroll
    for (int t = 0; t < 8; t++) {
        int f = lane + 32 * t;
        float xv = xr[f];
        __nv_bfloat16 h = __float2bfloat16(xv);
        g_xhi[(size_t)warp * NFEAT + f] = h;
        g_xlo[(size_t)warp * NFEAT + f] =
            __float2bfloat16(xv - __bfloat162float(h));
        #pragma unroll
        for (int c = 0; c < 4; c++) {
            pa[c] = fmaf(xv, asg_W1[c * 512 + f], pa[c]);
            pb[c] = fmaf(xv, asg_W1[c * 512 + 256 + f], pb[c]);
        }
    }
    #pragma unroll
    for (int c = 0; c < 4; c++)
        #pragma unroll
        for (int o = 16; o > 0; o >>= 1) {
            pa[c] += __shfl_xor_sync(0xFFFFFFFFu, pa[c], o);
            pb[c] += __shfl_xor_sync(0xFFFFFFFFu, pb[c], o);
        }
    if (lane == 0) {
        #pragma unroll
        for (int c = 0; c < 4; c++) {
            g_proj[warp * 8 + c]     = pa[c];
            g_proj[warp * 8 + 4 + c] = pb[c];
        }
    }
}

// ---------------- c = X @ CW^T + cb  via mma.sync bf16 split ----------------
#define CHK 32
#define PITCH 80
#define T_AH 0
#define T_AL (128 * PITCH)
#define T_BH (2 * 128 * PITCH)
#define T_BL (3 * 128 * PITCH)
#define STAGE_BYTES (4 * 128 * PITCH)
#define SM_DYN (2 * STAGE_BYTES)
#define NCHUNK (NFEAT / CHK)

__global__ __launch_bounds__(256, 2)
void k_cmma(int N) {
    extern __shared__ __align__(16) char sm[];
    uint32_t sb = smem_u32(sm);
    int tid  = threadIdx.x;
    int wid  = tid >> 5;
    int lane = tid & 31;
    int m0 = blockIdx.x * 128;
    int n0 = blockIdx.y * 128;
    int warp_m = wid >> 1;
    int warp_n = wid & 1;

    float acc[2][8][4];
    #pragma unroll
    for (int i = 0; i < 2; i++)
        #pragma unroll
        for (int j = 0; j < 8; j++)
            #pragma unroll
            for (int q = 0; q < 4; q++) acc[i][j][q] = 0.f;

    int a_row = warp_m * 32 + (lane & 15);
    int a_col = (lane >> 4) << 3;
    uint32_t aoff = (uint32_t)(a_row * PITCH + a_col * 2);
    int b_row_base = warp_n * 64 + ((lane >> 4) << 3) + (lane & 7);
    int b_col = ((lane >> 3) & 1) << 3;
    uint32_t boff = (uint32_t)(b_row_base * PITCH + b_col * 2);

    int lrow = tid >> 2;
    int lseg = tid & 3;

    auto load_stage = [&](int s, int k0) {
        uint32_t sgb = sb + (uint32_t)(s * STAGE_BYTES);
        #pragma unroll
        for (int ps = 0; ps < 2; ps++) {
            int r = lrow + ps * 64;
            uint32_t dst = sgb + (uint32_t)(r * PITCH + lseg * 16);
            int gm = m0 + r;
            int inb = gm < N;
            const __nv_bfloat16* ah = g_xhi + (size_t)(inb ? gm : 0) * NFEAT + k0 + lseg * 8;
            const __nv_bfloat16* al = g_xlo + (size_t)(inb ? gm : 0) * NFEAT + k0 + lseg * 8;
            cp16z(dst + T_AH, ah, inb);
            cp16z(dst + T_AL, al, inb);
            int gn = n0 + r;
            cp16(dst + T_BH, g_cwhi + (size_t)gn * NFEAT + k0 + lseg * 8);
            cp16(dst + T_BL, g_cwlo + (size_t)gn * NFEAT + k0 + lseg * 8);
        }
        asm volatile("cp.async.commit_group;");
    };

    load_stage(0, 0);

    #pragma unroll 1
    for (int chunk = 0; chunk < NCHUNK; chunk++) {
        int s = chunk & 1;
        asm volatile("cp.async.wait_group 0;" ::: "memory");
        __syncthreads();
        if (chunk + 1 < NCHUNK) load_stage(s ^ 1, (chunk + 1) * CHK);

        uint32_t sgb = sb + (uint32_t)(s * STAGE_BYTES);
        #pragma unroll
        for (int ka = 0; ka < CHK / 16; ka++) {
            uint32_t kb = (uint32_t)(ka * 16 * 2);
            uint32_t ah[2][4], al[2][4];
            #pragma unroll
            for (int i = 0; i < 2; i++) {
                uint32_t aa = sgb + aoff + kb + (uint32_t)(i * 16 * PITCH);
                ldsm4(aa + T_AH, ah[i][0], ah[i][1], ah[i][2], ah[i][3]);
                ldsm4(aa + T_AL, al[i][0], al[i][1], al[i][2], al[i][3]);
            }
            #pragma unroll
            for (int jp = 0; jp < 4; jp++) {
                uint32_t ba = sgb + boff + kb + (uint32_t)(jp * 16 * PITCH);
                uint32_t bh[4], bl[4];
                ldsm4(ba + T_BH, bh[0], bh[1], bh[2], bh[3]);
                ldsm4(ba + T_BL, bl[0], bl[1], bl[2], bl[3]);
                #pragma unroll
                for (int i = 0; i < 2; i++) {
                    float* c0 = acc[i][2 * jp];
                    float* c1 = acc[i][2 * jp + 1];
                    mma16816(c0, ah[i][0], ah[i][1], ah[i][2], ah[i][3], bh[0], bh[1]);
                    mma16816(c0, al[i][0], al[i][1], al[i][2], al[i][3], bh[0], bh[1]);
                    mma16816(c0, ah[i][0], ah[i][1], ah[i][2], ah[i][3], bl[0], bl[1]);
                    mma16816(c1, ah[i][0], ah[i][1], ah[i][2], ah[i][3], bh[2], bh[3]);
                    mma16816(c1, al[i][0], al[i][1], al[i][2], al[i][3], bh[2], bh[3]);
                    mma16816(c1, ah[i][0], ah[i][1], ah[i][2], ah[i][3], bl[2], bl[3]);
                }
            }
        }
        __syncthreads();
    }

    int g = lane >> 2, t4 = lane & 3;
    #pragma unroll
    for (int i = 0; i < 2; i++) {
        int row0 = m0 + warp_m * 32 + i * 16 + g;
        #pragma unroll
        for (int j = 0; j < 8; j++) {
            int col = n0 + warp_n * 64 + j * 8 + 2 * t4;
            float cb0 = g_cb[col], cb1 = g_cb[col + 1];
            if (row0 < N) {
                float2 v = make_float2(acc[i][j][0] + cb0, acc[i][j][1] + cb1);
                *(float2*)(g_c + (size_t)row0 * HIDDEN + col) = v;
            }
            if (row0 + 8 < N) {
                float2 v = make_float2(acc[i][j][2] + cb0, acc[i][j][3] + cb1);
                *(float2*)(g_c + (size_t)(row0 + 8) * HIDDEN + col) = v;
            }
        }
    }
}

// ---------------- CSR build ----------------
__global__ void k_zero(int N) {
    int i = blockIdx.x * blockDim.x + threadIdx.x;
    if (i < N) g_counts[i] = 0;
}

__global__ void k_hist(const void* __restrict__ rowp, int E) {
    int e = blockIdx.x * blockDim.x + threadIdx.x;
    if (e >= E) return;
    int r = g_is64 ? (int)((const long long*)rowp)[e] : ((const int*)rowp)[e];
    atomicAdd(&g_counts[r], 1);
}

// coalesced 3-phase scan
__global__ void k_bsum(int N) {
    __shared__ int sh[256];
    int t = threadIdx.x;
    int i = blockIdx.x * 256 + t;
    sh[t] = (i < N) ? g_counts[i] : 0;
    __syncthreads();
    #pragma unroll
    for (int o = 128; o > 0; o >>= 1) {
        if (t < o) sh[t] += sh[t + o];
        __syncthreads();
    }
    if (t == 0) g_bsum[blockIdx.x] = sh[0];
}

__global__ void k_bscan(int nb) {
    __shared__ int sh[512];
    int t = threadIdx.x;
    int v = (t < nb) ? g_bsum[t] : 0;
    sh[t] = v;
    __syncthreads();
    int acc = v;
    #pragma unroll
    for (int o = 1; o < 512; o <<= 1) {
        int u = (t >= o) ? sh[t - o] : 0;
        __syncthreads();
        acc += u;
        sh[t] = acc;
        __syncthreads();
    }
    if (t < nb) g_boff[t] = acc - v;   // exclusive
}

__global__ void k_rows(int N) {
    __shared__ int sh[256];
    int t = threadIdx.x;
    int i = blockIdx.x * 256 + t;
    int v = (i < N) ? g_counts[i] : 0;
    sh[t] = v;
    __syncthreads();
    int acc = v;
    #pragma unroll
    for (int o = 1; o < 256; o <<= 1) {
        int u = (t >= o) ? sh[t - o] : 0;
        __syncthreads();
        acc += u;
        sh[t] = acc;
        __syncthreads();
    }
    if (i < N) {
        int start = g_boff[blockIdx.x] + acc - v;
        g_rowstart[i] = start;
        g_cursor[i]   = start;
    }
}

__global__ void k_scatter(const void* __restrict__ rowp,
                          const void* __restrict__ colp, int E) {
    int e = blockIdx.x * blockDim.x + threadIdx.x;
    if (e >= E) return;
    int r, c;
    if (g_is64) {
        r = (int)((const long long*)rowp)[e];
        c = (int)((const long long*)colp)[e];
    } else {
        r = ((const int*)rowp)[e];
        c = ((const int*)colp)[e];
    }
    int pos = atomicAdd(&g_cursor[r], 1);
    g_csrcol[pos] = c;
}

// ---------------- fused aggregate + bias + norm + classifier ----------------
// TWO warps per row: warp-pair (wid&1 = half) each owns 128 cols, lane owns
// one float4 (16B per edge). Weights computed redundantly per warp (no
// cross-warp sync in the loop). Logits partials combined via smem.
__global__ __launch_bounds__(256)
void k_agg(const float* __restrict__ asg_b1, const float* __restrict__ asg_W2,
           const float* __restrict__ asg_b2, const float* __restrict__ bias,
           const float* __restrict__ cls_W, const float* __restrict__ cls_b,
           float* __restrict__ hout, float* __restrict__ logits, int N) {
    __shared__ float sw[8][32][4];
    __shared__ int   sc[8][32];
    __shared__ float slp[8][4];

    int wid   = threadIdx.x >> 5;
    int lane  = threadIdx.x & 31;
    int rslot = wid >> 1;
    int half  = wid & 1;
    int r     = blockIdx.x * 4 + rslot;
    bool active = (r < N);

    float lpf[4] = {0, 0, 0, 0};

    if (active) {
        float b1[4], b2r[4], W2[16];
        #pragma unroll
        for (int k = 0; k < 4; k++) { b1[k] = __ldg(asg_b1 + k); b2r[k] = __ldg(asg_b2 + k); }
        #pragma unroll
        for (int k = 0; k < 16; k++) W2[k] = __ldg(asg_W2 + k);

        float4 pbv = *(const float4*)(g_proj + r * 8 + 4);
        float pb[4] = {pbv.x, pbv.y, pbv.z, pbv.w};

        int start = g_rowstart[r];
        int deg   = g_counts[r];
        int colbase = half * 128 + lane * 4;   // first of this lane's 4 cols
        int myg     = colbase >> 6;            // group index (all 4 cols same group)

        ull ap0 = 0ull, ap1 = 0ull;

        for (int base = 0; base < deg; base += 32) {
            int cnt = deg - base; if (cnt > 32) cnt = 32;
            float w0 = 0.f, w1 = 0.f, w2 = 0.f, w3 = 0.f;
            int   mycol = 0;
            if (lane < cnt) {
                mycol = g_csrcol[start + base + lane];
                float4 pav = __ldg((const float4*)(g_proj + (size_t)mycol * 8));
                float h1[4] = {pav.x + pb[0] + b1[0], pav.y + pb[1] + b1[1],
                               pav.z + pb[2] + b1[2], pav.w + pb[3] + b1[3]};
                float h2[4], mx = -1e30f;
                #pragma unroll
                for (int k = 0; k < 4; k++) {
                    float s = b2r[k];
                    #pragma unroll
                    for (int d = 0; d < 4; d++) s = fmaf(h1[d], W2[k*4+d], s);
                    h2[k] = s; mx = fmaxf(mx, s);
                }
                float e0 = __expf(h2[0]-mx), e1 = __expf(h2[1]-mx);
                float e2 = __expf(h2[2]-mx), e3 = __expf(h2[3]-mx);
                float inv = 1.f / (e0+e1+e2+e3);
                w0 = e0*inv; w1 = e1*inv; w2 = e2*inv; w3 = e3*inv;
            }
            sw[wid][lane][0] = w0; sw[wid][lane][1] = w1;
            sw[wid][lane][2] = w2; sw[wid][lane][3] = w3;
            sc[wid][lane] = mycol;
            __syncwarp();

            #pragma unroll 8
            for (int j = 0; j < cnt; j++) {
                int   cj = sc[wid][j];
                float wj = sw[wid][j][myg];
                ull   wj2 = pack2(wj, wj);
                const ulonglong2* cr =
                    (const ulonglong2*)(g_c + (size_t)cj * HIDDEN + half * 128) + lane;
                ulonglong2 v = __ldg(cr);
                ffma2(ap0, v.x, wj2);
                ffma2(ap1, v.y, wj2);
            }
            __syncwarp();
        }

        float a[4];
        unpack2(ap0, a[0], a[1]);
        unpack2(ap1, a[2], a[3]);

        float4 bb = __ldg((const float4*)bias + half * 32 + lane);
        a[0] += bb.x; a[1] += bb.y; a[2] += bb.z; a[3] += bb.w;

        // per-group L2 norm: group = 64 cols = 16 contiguous lanes of this warp
        float ss = a[0]*a[0] + a[1]*a[1] + a[2]*a[2] + a[3]*a[3];
        #pragma unroll
        for (int o = 1; o < 16; o <<= 1)
            ss += __shfl_xor_sync(0xFFFFFFFFu, ss, o);
        float invn = 1.f / fmaxf(sqrtf(ss), 1e-12f);
        a[0] *= invn; a[1] *= invn; a[2] *= invn; a[3] *= invn;

        ((float4*)(hout + (size_t)r * HIDDEN + half * 128))[lane] =
            make_float4(a[0], a[1], a[2], a[3]);

        // logits partial over this warp's 128 cols
        #pragma unroll
        for (int cc = 0; cc < 4; cc++) {
            float4 cw = __ldg((const float4*)(cls_W + cc * HIDDEN + half * 128) + lane);
            lpf[cc] = a[0]*cw.x + a[1]*cw.y + a[2]*cw.z + a[3]*cw.w;
        }
        #pragma unroll
        for (int cc = 0; cc < 4; cc++)
            #pragma unroll
            for (int o = 16; o > 0; o >>= 1)
                lpf[cc] += __shfl_xor_sync(0xFFFFFFFFu, lpf[cc], o);
        if (lane == 0) {
            #pragma unroll
            for (int cc = 0; cc < 4; cc++) slp[wid][cc] = lpf[cc];
        }
    }
    __syncthreads();
    if (active && half == 0 && lane == 0) {
        #pragma unroll
        for (int cc = 0; cc < 4; cc++)
            logits[(size_t)r * NCLASS + cc] =
                slp[wid][cc] + slp[wid + 1][cc] + __ldg(cls_b + cc);
    }
}

// ---------------- launch ----------------
extern "C" void kernel_launch(void* const* d_in, const int* in_sizes, int n_in,
                              void* d_out, int out_size) {
    const float* x      = (const float*)d_in[0];
    const void*  rowp   = d_in[1];
    const void*  colp   = d_in[2];
    const float* asg_W1 = (const float*)d_in[3];
    const float* asg_b1 = (const float*)d_in[4];
    const float* asg_W2 = (const float*)d_in[5];
    const float* asg_b2 = (const float*)d_in[6];
    const float* lin_W  = (const float*)d_in[7];
    const float* lin_b  = (const float*)d_in[8];
    const float* conv_W = (const float*)d_in[9];
    const float* bias   = (const float*)d_in[10];
    const float* cls_W  = (const float*)d_in[11];
    const float* cls_b  = (const float*)d_in[12];

    int N = in_sizes[0] / NFEAT;
    int E = in_sizes[1];
    int nb = (N + 255) / 256;

    float* hout   = (float*)d_out;
    float* logits = hout + (size_t)N * HIDDEN;

    cudaFuncSetAttribute(k_cmma, cudaFuncAttributeMaxDynamicSharedMemorySize,
                         SM_DYN);

    k_detect<<<1, 32>>>((const unsigned int*)rowp, E);
    k_fold<<<HIDDEN, NFEAT>>>(conv_W, lin_W, lin_b);
    k_proj<<<(N + 7) / 8, 256>>>(x, asg_W1, N);
    dim3 gg((N + 127) / 128, HIDDEN / 128);
    k_cmma<<<gg, 256, SM_DYN>>>(N);
    k_zero<<<(N + 255) / 256, 256>>>(N);
    k_hist<<<(E + 255) / 256, 256>>>(rowp, E);
    k_bsum<<<nb, 256>>>(N);
    k_bscan<<<1, 512>>>(nb);
    k_rows<<<nb, 256>>>(N);
    k_scatter<<<(E + 255) / 256, 256>>>(rowp, colp, E);
    k_agg<<<(N + 3) / 4, 256>>>(asg_b1, asg_W2, asg_b2, bias,
                                cls_W, cls_b, hout, logits, N);
}

// round 12
// speedup vs baseline: 1.3586x; 1.3586x over previous
#include <cuda_runtime.h>
#include <cuda_bf16.h>
#include <math.h>
#include <cstdint>

#define NFEAT   256
#define HIDDEN  256
#define PCH     64
#define NCLASS  4
#define MAXN    100000
#define MAXE    1600000

typedef unsigned long long ull;

__device__ __forceinline__ ull pack2(float x, float y) {
    ull r; asm("mov.b64 %0, {%1,%2};" : "=l"(r) : "f"(x), "f"(y)); return r;
}
__device__ __forceinline__ void unpack2(ull v, float& x, float& y) {
    asm("mov.b64 {%0,%1}, %2;" : "=f"(x), "=f"(y) : "l"(v));
}
__device__ __forceinline__ void ffma2(ull& d, ull a, ull b) {
    asm("fma.rn.f32x2 %0, %1, %2, %0;" : "+l"(d) : "l"(a), "l"(b));
}
__device__ __forceinline__ uint32_t smem_u32(const void* p) {
    uint32_t a;
    asm("{ .reg .u64 t; cvta.to.shared.u64 t, %1; cvt.u32.u64 %0, t; }"
        : "=r"(a) : "l"(p));
    return a;
}
__device__ __forceinline__ void ldsm4(uint32_t addr, uint32_t& r0, uint32_t& r1,
                                      uint32_t& r2, uint32_t& r3) {
    asm volatile("ldmatrix.sync.aligned.m8n8.x4.shared.b16 {%0,%1,%2,%3}, [%4];"
                 : "=r"(r0), "=r"(r1), "=r"(r2), "=r"(r3) : "r"(addr));
}
__device__ __forceinline__ void mma16816(float* c, uint32_t a0, uint32_t a1,
                                         uint32_t a2, uint32_t a3,
                                         uint32_t b0, uint32_t b1) {
    asm volatile(
        "mma.sync.aligned.m16n8k16.row.col.f32.bf16.bf16.f32 "
        "{%0,%1,%2,%3}, {%4,%5,%6,%7}, {%8,%9}, {%0,%1,%2,%3};"
        : "+f"(c[0]), "+f"(c[1]), "+f"(c[2]), "+f"(c[3])
        : "r"(a0), "r"(a1), "r"(a2), "r"(a3), "r"(b0), "r"(b1));
}
__device__ __forceinline__ void cp16z(uint32_t dst, const void* src, int inb) {
    int sz = inb ? 16 : 0;
    asm volatile("cp.async.cg.shared.global [%0], [%1], 16, %2;"
                 :: "r"(dst), "l"(src), "r"(sz));
}
__device__ __forceinline__ void cp16(uint32_t dst, const void* src) {
    asm volatile("cp.async.cg.shared.global [%0], [%1], 16;"
                 :: "r"(dst), "l"(src));
}

// ---------------- device scratch ----------------
__device__ int   g_is64;
__device__ float g_cb[HIDDEN];
__device__ float g_proj[MAXN * 8];
__device__ float g_c[(size_t)MAXN * HIDDEN];
__device__ __nv_bfloat16 g_xhi[(size_t)MAXN * NFEAT];
__device__ __nv_bfloat16 g_xlo[(size_t)MAXN * NFEAT];
__device__ __nv_bfloat16 g_cwhi[HIDDEN * NFEAT];
__device__ __nv_bfloat16 g_cwlo[HIDDEN * NFEAT];
__device__ int   g_counts[MAXN];
__device__ int   g_rowstart[MAXN];
__device__ int   g_cursor[MAXN];
__device__ int   g_csrcol[MAXE];
__device__ int   g_epos[MAXE];
__device__ float4 g_w[MAXE];
__device__ int   g_bsum[512];
__device__ int   g_boff[512];

// ---------------- index width sniffing ----------------
__global__ void k_detect(const unsigned int* __restrict__ rowp, int E) {
    if (threadIdx.x == 0 && blockIdx.x == 0) {
        int n = E < 64 ? E : 64;
        int all_hi_zero = 1;
        for (int i = 0; i < n; i++)
            if (rowp[2 * i + 1] != 0u) { all_hi_zero = 0; break; }
        g_is64 = all_hi_zero;
    }
}

// ---------------- fold conv into lin, output bf16 hi/lo ----------------
__global__ void k_fold(const float* __restrict__ conv_W,
                       const float* __restrict__ lin_W,
                       const float* __restrict__ lin_b) {
    int t = blockIdx.x, f = threadIdx.x;
    int k = t >> 6, q = t & 63;
    const float* cw = conv_W + (k * PCH + q) * PCH;
    const float* lw = lin_W + (size_t)k * PCH * NFEAT;
    float s = 0.f;
    #pragma unroll 8
    for (int p = 0; p < PCH; p++) s = fmaf(cw[p], lw[p * NFEAT + f], s);
    __nv_bfloat16 hi = __float2bfloat16(s);
    g_cwhi[t * NFEAT + f] = hi;
    g_cwlo[t * NFEAT + f] = __float2bfloat16(s - __bfloat162float(hi));
    if (f == 0) {
        const float* lb = lin_b + k * PCH;
        float b = 0.f;
        for (int p = 0; p < PCH; p++) b = fmaf(cw[p], lb[p], b);
        g_cb[t] = b;
    }
}

// ---------------- projections + x split (single x read) ----------------
__global__ void k_proj(const float* __restrict__ x,
                       const float* __restrict__ asg_W1, int N) {
    int warp = (blockIdx.x * blockDim.x + threadIdx.x) >> 5;
    int lane = threadIdx.x & 31;
    if (warp >= N) return;
    const float* xr = x + (size_t)warp * NFEAT;
    float pa[4] = {0,0,0,0}, pb[4] = {0,0,0,0};
    #pragma unroll
    for (int t = 0; t < 8; t++) {
        int f = lane + 32 * t;
        float xv = xr[f];
        __nv_bfloat16 h = __float2bfloat16(xv);
        g_xhi[(size_t)warp * NFEAT + f] = h;
        g_xlo[(size_t)warp * NFEAT + f] =
            __float2bfloat16(xv - __bfloat162float(h));
        #pragma unroll
        for (int c = 0; c < 4; c++) {
            pa[c] = fmaf(xv, asg_W1[c * 512 + f], pa[c]);
            pb[c] = fmaf(xv, asg_W1[c * 512 + 256 + f], pb[c]);
        }
    }
    #pragma unroll
    for (int c = 0; c < 4; c++)
        #pragma unroll
        for (int o = 16; o > 0; o >>= 1) {
            pa[c] += __shfl_xor_sync(0xFFFFFFFFu, pa[c], o);
            pb[c] += __shfl_xor_sync(0xFFFFFFFFu, pb[c], o);
        }
    if (lane == 0) {
        #pragma unroll
        for (int c = 0; c < 4; c++) {
            g_proj[warp * 8 + c]     = pa[c];
            g_proj[warp * 8 + 4 + c] = pb[c];
        }
    }
}

// ---------------- c = X @ CW^T + cb  via mma.sync bf16 split ----------------
#define CHK 32
#define PITCH 80
#define T_AH 0
#define T_AL (128 * PITCH)
#define T_BH (2 * 128 * PITCH)
#define T_BL (3 * 128 * PITCH)
#define STAGE_BYTES (4 * 128 * PITCH)
#define SM_DYN (2 * STAGE_BYTES)
#define NCHUNK (NFEAT / CHK)

__global__ __launch_bounds__(256, 2)
void k_cmma(int N) {
    extern __shared__ __align__(16) char sm[];
    uint32_t sb = smem_u32(sm);
    int tid  = threadIdx.x;
    int wid  = tid >> 5;
    int lane = tid & 31;
    int m0 = blockIdx.x * 128;
    int n0 = blockIdx.y * 128;
    int warp_m = wid >> 1;
    int warp_n = wid & 1;

    float acc[2][8][4];
    #pragma unroll
    for (int i = 0; i < 2; i++)
        #pragma unroll
        for (int j = 0; j < 8; j++)
            #pragma unroll
            for (int q = 0; q < 4; q++) acc[i][j][q] = 0.f;

    int a_row = warp_m * 32 + (lane & 15);
    int a_col = (lane >> 4) << 3;
    uint32_t aoff = (uint32_t)(a_row * PITCH + a_col * 2);
    int b_row_base = warp_n * 64 + ((lane >> 4) << 3) + (lane & 7);
    int b_col = ((lane >> 3) & 1) << 3;
    uint32_t boff = (uint32_t)(b_row_base * PITCH + b_col * 2);

    int lrow = tid >> 2;
    int lseg = tid & 3;

    auto load_stage = [&](int s, int k0) {
        uint32_t sgb = sb + (uint32_t)(s * STAGE_BYTES);
        #pragma unroll
        for (int ps = 0; ps < 2; ps++) {
            int r = lrow + ps * 64;
            uint32_t dst = sgb + (uint32_t)(r * PITCH + lseg * 16);
            int gm = m0 + r;
            int inb = gm < N;
            const __nv_bfloat16* ah = g_xhi + (size_t)(inb ? gm : 0) * NFEAT + k0 + lseg * 8;
            const __nv_bfloat16* al = g_xlo + (size_t)(inb ? gm : 0) * NFEAT + k0 + lseg * 8;
            cp16z(dst + T_AH, ah, inb);
            cp16z(dst + T_AL, al, inb);
            int gn = n0 + r;
            cp16(dst + T_BH, g_cwhi + (size_t)gn * NFEAT + k0 + lseg * 8);
            cp16(dst + T_BL, g_cwlo + (size_t)gn * NFEAT + k0 + lseg * 8);
        }
        asm volatile("cp.async.commit_group;");
    };

    load_stage(0, 0);

    #pragma unroll 1
    for (int chunk = 0; chunk < NCHUNK; chunk++) {
        int s = chunk & 1;
        asm volatile("cp.async.wait_group 0;" ::: "memory");
        __syncthreads();
        if (chunk + 1 < NCHUNK) load_stage(s ^ 1, (chunk + 1) * CHK);

        uint32_t sgb = sb + (uint32_t)(s * STAGE_BYTES);
        #pragma unroll
        for (int ka = 0; ka < CHK / 16; ka++) {
            uint32_t kb = (uint32_t)(ka * 16 * 2);
            uint32_t ah[2][4], al[2][4];
            #pragma unroll
            for (int i = 0; i < 2; i++) {
                uint32_t aa = sgb + aoff + kb + (uint32_t)(i * 16 * PITCH);
                ldsm4(aa + T_AH, ah[i][0], ah[i][1], ah[i][2], ah[i][3]);
                ldsm4(aa + T_AL, al[i][0], al[i][1], al[i][2], al[i][3]);
            }
            #pragma unroll
            for (int jp = 0; jp < 4; jp++) {
                uint32_t ba = sgb + boff + kb + (uint32_t)(jp * 16 * PITCH);
                uint32_t bh[4], bl[4];
                ldsm4(ba + T_BH, bh[0], bh[1], bh[2], bh[3]);
                ldsm4(ba + T_BL, bl[0], bl[1], bl[2], bl[3]);
                #pragma unroll
                for (int i = 0; i < 2; i++) {
                    float* c0 = acc[i][2 * jp];
                    float* c1 = acc[i][2 * jp + 1];
                    mma16816(c0, ah[i][0], ah[i][1], ah[i][2], ah[i][3], bh[0], bh[1]);
                    mma16816(c0, al[i][0], al[i][1], al[i][2], al[i][3], bh[0], bh[1]);
                    mma16816(c0, ah[i][0], ah[i][1], ah[i][2], ah[i][3], bl[0], bl[1]);
                    mma16816(c1, ah[i][0], ah[i][1], ah[i][2], ah[i][3], bh[2], bh[3]);
                    mma16816(c1, al[i][0], al[i][1], al[i][2], al[i][3], bh[2], bh[3]);
                    mma16816(c1, ah[i][0], ah[i][1], ah[i][2], ah[i][3], bl[2], bl[3]);
                }
            }
        }
        __syncthreads();
    }

    int g = lane >> 2, t4 = lane & 3;
    #pragma unroll
    for (int i = 0; i < 2; i++) {
        int row0 = m0 + warp_m * 32 + i * 16 + g;
        #pragma unroll
        for (int j = 0; j < 8; j++) {
            int col = n0 + warp_n * 64 + j * 8 + 2 * t4;
            float cb0 = g_cb[col], cb1 = g_cb[col + 1];
            if (row0 < N) {
                float2 v = make_float2(acc[i][j][0] + cb0, acc[i][j][1] + cb1);
                *(float2*)(g_c + (size_t)row0 * HIDDEN + col) = v;
            }
            if (row0 + 8 < N) {
                float2 v = make_float2(acc[i][j][2] + cb0, acc[i][j][3] + cb1);
                *(float2*)(g_c + (size_t)(row0 + 8) * HIDDEN + col) = v;
            }
        }
    }
}

// ---------------- CSR build ----------------
__global__ void k_zero(int N) {
    int i = blockIdx.x * blockDim.x + threadIdx.x;
    if (i < N) g_counts[i] = 0;
}

__global__ void k_hist(const void* __restrict__ rowp, int E) {
    int e = blockIdx.x * blockDim.x + threadIdx.x;
    if (e >= E) return;
    int r = g_is64 ? (int)((const long long*)rowp)[e] : ((const int*)rowp)[e];
    atomicAdd(&g_counts[r], 1);
}

// coalesced 3-phase scan
__global__ void k_bsum(int N) {
    __shared__ int sh[256];
    int t = threadIdx.x;
    int i = blockIdx.x * 256 + t;
    sh[t] = (i < N) ? g_counts[i] : 0;
    __syncthreads();
    #pragma unroll
    for (int o = 128; o > 0; o >>= 1) {
        if (t < o) sh[t] += sh[t + o];
        __syncthreads();
    }
    if (t == 0) g_bsum[blockIdx.x] = sh[0];
}

__global__ void k_bscan(int nb) {
    __shared__ int sh[512];
    int t = threadIdx.x;
    int v = (t < nb) ? g_bsum[t] : 0;
    sh[t] = v;
    __syncthreads();
    int acc = v;
    #pragma unroll
    for (int o = 1; o < 512; o <<= 1) {
        int u = (t >= o) ? sh[t - o] : 0;
        __syncthreads();
        acc += u;
        sh[t] = acc;
        __syncthreads();
    }
    if (t < nb) g_boff[t] = acc - v;   // exclusive
}

__global__ void k_rows(int N) {
    __shared__ int sh[256];
    int t = threadIdx.x;
    int i = blockIdx.x * 256 + t;
    int v = (i < N) ? g_counts[i] : 0;
    sh[t] = v;
    __syncthreads();
    int acc = v;
    #pragma unroll
    for (int o = 1; o < 256; o <<= 1) {
        int u = (t >= o) ? sh[t - o] : 0;
        __syncthreads();
        acc += u;
        sh[t] = acc;
        __syncthreads();
    }
    if (i < N) {
        int start = g_boff[blockIdx.x] + acc - v;
        g_rowstart[i] = start;
        g_cursor[i]   = start;
    }
}

__global__ void k_scatter(const void* __restrict__ rowp,
                          const void* __restrict__ colp, int E) {
    int e = blockIdx.x * blockDim.x + threadIdx.x;
    if (e >= E) return;
    int r, c;
    if (g_is64) {
        r = (int)((const long long*)rowp)[e];
        c = (int)((const long long*)colp)[e];
    } else {
        r = ((const int*)rowp)[e];
        c = ((const int*)colp)[e];
    }
    int pos = atomicAdd(&g_cursor[r], 1);
    g_csrcol[pos] = c;
    g_epos[e] = pos;
}

// ---------------- per-edge softmax weights (original edge order) ----------------
__global__ void k_weights(const void* __restrict__ rowp,
                          const void* __restrict__ colp,
                          const float* __restrict__ asg_b1,
                          const float* __restrict__ asg_W2,
                          const float* __restrict__ asg_b2, int E) {
    int e = blockIdx.x * blockDim.x + threadIdx.x;
    if (e >= E) return;
    int r, c;
    if (g_is64) {
        r = (int)((const long long*)rowp)[e];
        c = (int)((const long long*)colp)[e];
    } else {
        r = ((const int*)rowp)[e];
        c = ((const int*)colp)[e];
    }
    float4 pav = __ldg((const float4*)(g_proj + (size_t)c * 8));
    float4 pbv = __ldg((const float4*)(g_proj + (size_t)r * 8 + 4));
    float h1[4] = {pav.x + pbv.x + __ldg(asg_b1 + 0),
                   pav.y + pbv.y + __ldg(asg_b1 + 1),
                   pav.z + pbv.z + __ldg(asg_b1 + 2),
                   pav.w + pbv.w + __ldg(asg_b1 + 3)};
    float h2[4], mx = -1e30f;
    #pragma unroll
    for (int k = 0; k < 4; k++) {
        float s = __ldg(asg_b2 + k);
        #pragma unroll
        for (int d = 0; d < 4; d++) s = fmaf(h1[d], __ldg(asg_W2 + k * 4 + d), s);
        h2[k] = s; mx = fmaxf(mx, s);
    }
    float e0 = __expf(h2[0]-mx), e1 = __expf(h2[1]-mx);
    float e2 = __expf(h2[2]-mx), e3 = __expf(h2[3]-mx);
    float inv = 1.f / (e0+e1+e2+e3);
    g_w[g_epos[e]] = make_float4(e0*inv, e1*inv, e2*inv, e3*inv);
}

// ---------------- fused aggregate + bias + norm + classifier ----------------
// one warp per row; weights precomputed (coalesced load from g_w in CSR order)
__global__ __launch_bounds__(256)
void k_agg(const float* __restrict__ bias,
           const float* __restrict__ cls_W, const float* __restrict__ cls_b,
           float* __restrict__ hout, float* __restrict__ logits, int N) {
    __shared__ float sw[8][32][4];
    __shared__ int   sc[8][32];

    int wid  = threadIdx.x >> 5;
    int lane = threadIdx.x & 31;
    int r    = blockIdx.x * 8 + wid;
    if (r >= N) return;

    int start = g_rowstart[r];
    int deg   = g_counts[r];
    int myg   = lane >> 3;

    ull ap0 = 0ull, ap1 = 0ull, ap2 = 0ull, ap3 = 0ull;

    for (int base = 0; base < deg; base += 32) {
        int cnt = deg - base; if (cnt > 32) cnt = 32;
        if (lane < cnt) {
            int idx = start + base + lane;
            sc[wid][lane] = g_csrcol[idx];
            float4 wv = __ldg(g_w + idx);
            sw[wid][lane][0] = wv.x; sw[wid][lane][1] = wv.y;
            sw[wid][lane][2] = wv.z; sw[wid][lane][3] = wv.w;
        }
        __syncwarp();

        #pragma unroll 8
        for (int j = 0; j < cnt; j++) {
            int   cj = sc[wid][j];
            float wj = sw[wid][j][myg];
            ull   wj2 = pack2(wj, wj);
            const ulonglong2* cr =
                (const ulonglong2*)(g_c + (size_t)cj * HIDDEN) + lane * 2;
            ulonglong2 v0 = __ldg(cr);
            ulonglong2 v1 = __ldg(cr + 1);
            ffma2(ap0, v0.x, wj2); ffma2(ap1, v0.y, wj2);
            ffma2(ap2, v1.x, wj2); ffma2(ap3, v1.y, wj2);
        }
        __syncwarp();
    }

    float a[8];
    unpack2(ap0, a[0], a[1]); unpack2(ap1, a[2], a[3]);
    unpack2(ap2, a[4], a[5]); unpack2(ap3, a[6], a[7]);

    float4 bb0 = __ldg((const float4*)bias + lane * 2);
    float4 bb1 = __ldg((const float4*)bias + lane * 2 + 1);
    a[0] += bb0.x; a[1] += bb0.y; a[2] += bb0.z; a[3] += bb0.w;
    a[4] += bb1.x; a[5] += bb1.y; a[6] += bb1.z; a[7] += bb1.w;

    float ss = 0.f;
    #pragma unroll
    for (int t = 0; t < 8; t++) ss = fmaf(a[t], a[t], ss);
    #pragma unroll
    for (int o = 1; o < 8; o <<= 1)
        ss += __shfl_xor_sync(0xFFFFFFFFu, ss, o);
    float invn = 1.f / fmaxf(sqrtf(ss), 1e-12f);
    #pragma unroll
    for (int t = 0; t < 8; t++) a[t] *= invn;

    float4* hr = (float4*)(hout + (size_t)r * HIDDEN) + lane * 2;
    hr[0] = make_float4(a[0], a[1], a[2], a[3]);
    hr[1] = make_float4(a[4], a[5], a[6], a[7]);

    float lp[4];
    #pragma unroll
    for (int cc = 0; cc < 4; cc++) {
        const float4* cwp = (const float4*)(cls_W + cc * HIDDEN) + lane * 2;
        float4 c0 = __ldg(cwp), c1 = __ldg(cwp + 1);
        lp[cc] = a[0]*c0.x + a[1]*c0.y + a[2]*c0.z + a[3]*c0.w
               + a[4]*c1.x + a[5]*c1.y + a[6]*c1.z + a[7]*c1.w;
    }
    #pragma unroll
    for (int cc = 0; cc < 4; cc++)
        #pragma unroll
        for (int o = 16; o > 0; o >>= 1)
            lp[cc] += __shfl_xor_sync(0xFFFFFFFFu, lp[cc], o);
    if (lane == 0) {
        #pragma unroll
        for (int cc = 0; cc < 4; cc++)
            logits[(size_t)r * NCLASS + cc] = lp[cc] + __ldg(cls_b + cc);
    }
}

// ---------------- launch ----------------
extern "C" void kernel_launch(void* const* d_in, const int* in_sizes, int n_in,
                              void* d_out, int out_size) {
    const float* x      = (const float*)d_in[0];
    const void*  rowp   = d_in[1];
    const void*  colp   = d_in[2];
    const float* asg_W1 = (const float*)d_in[3];
    const float* asg_b1 = (const float*)d_in[4];
    const float* asg_W2 = (const float*)d_in[5];
    const float* asg_b2 = (const float*)d_in[6];
    const float* lin_W  = (const float*)d_in[7];
    const float* lin_b  = (const float*)d_in[8];
    const float* conv_W = (const float*)d_in[9];
    const float* bias   = (const float*)d_in[10];
    const float* cls_W  = (const float*)d_in[11];
    const float* cls_b  = (const float*)d_in[12];

    int N = in_sizes[0] / NFEAT;
    int E = in_sizes[1];
    int nb = (N + 255) / 256;

    float* hout   = (float*)d_out;
    float* logits = hout + (size_t)N * HIDDEN;

    cudaFuncSetAttribute(k_cmma, cudaFuncAttributeMaxDynamicSharedMemorySize,
                         SM_DYN);

    k_detect<<<1, 32>>>((const unsigned int*)rowp, E);
    k_fold<<<HIDDEN, NFEAT>>>(conv_W, lin_W, lin_b);
    k_proj<<<(N + 7) / 8, 256>>>(x, asg_W1, N);
    dim3 gg((N + 127) / 128, HIDDEN / 128);
    k_cmma<<<gg, 256, SM_DYN>>>(N);
    k_zero<<<(N + 255) / 256, 256>>>(N);
    k_hist<<<(E + 255) / 256, 256>>>(rowp, E);
    k_bsum<<<nb, 256>>>(N);
    k_bscan<<<1, 512>>>(nb);
    k_rows<<<nb, 256>>>(N);
    k_scatter<<<(E + 255) / 256, 256>>>(rowp, colp, E);
    k_weights<<<(E + 255) / 256, 256>>>(rowp, colp, asg_b1, asg_W2, asg_b2, E);
    k_agg<<<(N + 7) / 8, 256>>>(bias, cls_W, cls_b, hout, logits, N);
}

// round 13
// speedup vs baseline: 1.5727x; 1.1575x over previous
#include <cuda_runtime.h>
#include <cuda_bf16.h>
#include <cuda_fp16.h>
#include <math.h>
#include <cstdint>

#define NFEAT   256
#define HIDDEN  256
#define PCH     64
#define NCLASS  4
#define MAXN    100000
#define MAXE    1600000

typedef unsigned long long ull;

__device__ __forceinline__ uint32_t smem_u32(const void* p) {
    uint32_t a;
    asm("{ .reg .u64 t; cvta.to.shared.u64 t, %1; cvt.u32.u64 %0, t; }"
        : "=r"(a) : "l"(p));
    return a;
}
__device__ __forceinline__ void ldsm4(uint32_t addr, uint32_t& r0, uint32_t& r1,
                                      uint32_t& r2, uint32_t& r3) {
    asm volatile("ldmatrix.sync.aligned.m8n8.x4.shared.b16 {%0,%1,%2,%3}, [%4];"
                 : "=r"(r0), "=r"(r1), "=r"(r2), "=r"(r3) : "r"(addr));
}
__device__ __forceinline__ void mma16816(float* c, uint32_t a0, uint32_t a1,
                                         uint32_t a2, uint32_t a3,
                                         uint32_t b0, uint32_t b1) {
    asm volatile(
        "mma.sync.aligned.m16n8k16.row.col.f32.bf16.bf16.f32 "
        "{%0,%1,%2,%3}, {%4,%5,%6,%7}, {%8,%9}, {%0,%1,%2,%3};"
        : "+f"(c[0]), "+f"(c[1]), "+f"(c[2]), "+f"(c[3])
        : "r"(a0), "r"(a1), "r"(a2), "r"(a3), "r"(b0), "r"(b1));
}
__device__ __forceinline__ void cp16z(uint32_t dst, const void* src, int inb) {
    int sz = inb ? 16 : 0;
    asm volatile("cp.async.cg.shared.global [%0], [%1], 16, %2;"
                 :: "r"(dst), "l"(src), "r"(sz));
}
__device__ __forceinline__ void cp16(uint32_t dst, const void* src) {
    asm volatile("cp.async.cg.shared.global [%0], [%1], 16;"
                 :: "r"(dst), "l"(src));
}

// ---------------- device scratch ----------------
__device__ int   g_is64;
__device__ float g_cb[HIDDEN];
__device__ float g_proj[MAXN * 8];
__device__ __half g_ch[(size_t)MAXN * HIDDEN];      // fp16 message matrix
__device__ __nv_bfloat16 g_xhi[(size_t)MAXN * NFEAT];
__device__ __nv_bfloat16 g_xlo[(size_t)MAXN * NFEAT];
__device__ __nv_bfloat16 g_cwhi[HIDDEN * NFEAT];
__device__ __nv_bfloat16 g_cwlo[HIDDEN * NFEAT];
__device__ int   g_counts[MAXN];
__device__ int   g_rowstart[MAXN];
__device__ int   g_cursor[MAXN];
__device__ int   g_csrcol[MAXE];
__device__ float4 g_w[MAXE];
__device__ int   g_bsum[512];
__device__ int   g_boff[512];

// ---------------- index width sniffing ----------------
__global__ void k_detect(const unsigned int* __restrict__ rowp, int E) {
    if (threadIdx.x == 0 && blockIdx.x == 0) {
        int n = E < 64 ? E : 64;
        int all_hi_zero = 1;
        for (int i = 0; i < n; i++)
            if (rowp[2 * i + 1] != 0u) { all_hi_zero = 0; break; }
        g_is64 = all_hi_zero;
    }
}

// ---------------- fold conv into lin, output bf16 hi/lo ----------------
__global__ void k_fold(const float* __restrict__ conv_W,
                       const float* __restrict__ lin_W,
                       const float* __restrict__ lin_b) {
    int t = blockIdx.x, f = threadIdx.x;
    int k = t >> 6, q = t & 63;
    const float* cw = conv_W + (k * PCH + q) * PCH;
    const float* lw = lin_W + (size_t)k * PCH * NFEAT;
    float s = 0.f;
    #pragma unroll 8
    for (int p = 0; p < PCH; p++) s = fmaf(cw[p], lw[p * NFEAT + f], s);
    __nv_bfloat16 hi = __float2bfloat16(s);
    g_cwhi[t * NFEAT + f] = hi;
    g_cwlo[t * NFEAT + f] = __float2bfloat16(s - __bfloat162float(hi));
    if (f == 0) {
        const float* lb = lin_b + k * PCH;
        float b = 0.f;
        for (int p = 0; p < PCH; p++) b = fmaf(cw[p], lb[p], b);
        g_cb[t] = b;
    }
}

// ---------------- projections + x split (single x read) ----------------
__global__ void k_proj(const float* __restrict__ x,
                       const float* __restrict__ asg_W1, int N) {
    int warp = (blockIdx.x * blockDim.x + threadIdx.x) >> 5;
    int lane = threadIdx.x & 31;
    if (warp >= N) return;
    const float* xr = x + (size_t)warp * NFEAT;
    float pa[4] = {0,0,0,0}, pb[4] = {0,0,0,0};
    #pragma unroll
    for (int t = 0; t < 8; t++) {
        int f = lane + 32 * t;
        float xv = xr[f];
        __nv_bfloat16 h = __float2bfloat16(xv);
        g_xhi[(size_t)warp * NFEAT + f] = h;
        g_xlo[(size_t)warp * NFEAT + f] =
            __float2bfloat16(xv - __bfloat162float(h));
        #pragma unroll
        for (int c = 0; c < 4; c++) {
            pa[c] = fmaf(xv, asg_W1[c * 512 + f], pa[c]);
            pb[c] = fmaf(xv, asg_W1[c * 512 + 256 + f], pb[c]);
        }
    }
    #pragma unroll
    for (int c = 0; c < 4; c++)
        #pragma unroll
        for (int o = 16; o > 0; o >>= 1) {
            pa[c] += __shfl_xor_sync(0xFFFFFFFFu, pa[c], o);
            pb[c] += __shfl_xor_sync(0xFFFFFFFFu, pb[c], o);
        }
    if (lane == 0) {
        #pragma unroll
        for (int c = 0; c < 4; c++) {
            g_proj[warp * 8 + c]     = pa[c];
            g_proj[warp * 8 + 4 + c] = pb[c];
        }
    }
}

// ---------------- c = X @ CW^T + cb  via mma.sync bf16 split ----------------
#define CHK 32
#define PITCH 80
#define T_AH 0
#define T_AL (128 * PITCH)
#define T_BH (2 * 128 * PITCH)
#define T_BL (3 * 128 * PITCH)
#define STAGE_BYTES (4 * 128 * PITCH)
#define SM_DYN (2 * STAGE_BYTES)
#define NCHUNK (NFEAT / CHK)

__global__ __launch_bounds__(256, 2)
void k_cmma(int N) {
    extern __shared__ __align__(16) char sm[];
    uint32_t sb = smem_u32(sm);
    int tid  = threadIdx.x;
    int wid  = tid >> 5;
    int lane = tid & 31;
    int m0 = blockIdx.x * 128;
    int n0 = blockIdx.y * 128;
    int warp_m = wid >> 1;
    int warp_n = wid & 1;

    float acc[2][8][4];
    #pragma unroll
    for (int i = 0; i < 2; i++)
        #pragma unroll
        for (int j = 0; j < 8; j++)
            #pragma unroll
            for (int q = 0; q < 4; q++) acc[i][j][q] = 0.f;

    int a_row = warp_m * 32 + (lane & 15);
    int a_col = (lane >> 4) << 3;
    uint32_t aoff = (uint32_t)(a_row * PITCH + a_col * 2);
    int b_row_base = warp_n * 64 + ((lane >> 4) << 3) + (lane & 7);
    int b_col = ((lane >> 3) & 1) << 3;
    uint32_t boff = (uint32_t)(b_row_base * PITCH + b_col * 2);

    int lrow = tid >> 2;
    int lseg = tid & 3;

    auto load_stage = [&](int s, int k0) {
        uint32_t sgb = sb + (uint32_t)(s * STAGE_BYTES);
        #pragma unroll
        for (int ps = 0; ps < 2; ps++) {
            int r = lrow + ps * 64;
            uint32_t dst = sgb + (uint32_t)(r * PITCH + lseg * 16);
            int gm = m0 + r;
            int inb = gm < N;
            const __nv_bfloat16* ah = g_xhi + (size_t)(inb ? gm : 0) * NFEAT + k0 + lseg * 8;
            const __nv_bfloat16* al = g_xlo + (size_t)(inb ? gm : 0) * NFEAT + k0 + lseg * 8;
            cp16z(dst + T_AH, ah, inb);
            cp16z(dst + T_AL, al, inb);
            int gn = n0 + r;
            cp16(dst + T_BH, g_cwhi + (size_t)gn * NFEAT + k0 + lseg * 8);
            cp16(dst + T_BL, g_cwlo + (size_t)gn * NFEAT + k0 + lseg * 8);
        }
        asm volatile("cp.async.commit_group;");
    };

    load_stage(0, 0);

    #pragma unroll 1
    for (int chunk = 0; chunk < NCHUNK; chunk++) {
        int s = chunk & 1;
        asm volatile("cp.async.wait_group 0;" ::: "memory");
        __syncthreads();
        if (chunk + 1 < NCHUNK) load_stage(s ^ 1, (chunk + 1) * CHK);

        uint32_t sgb = sb + (uint32_t)(s * STAGE_BYTES);
        #pragma unroll
        for (int ka = 0; ka < CHK / 16; ka++) {
            uint32_t kb = (uint32_t)(ka * 16 * 2);
            uint32_t ah[2][4], al[2][4];
            #pragma unroll
            for (int i = 0; i < 2; i++) {
                uint32_t aa = sgb + aoff + kb + (uint32_t)(i * 16 * PITCH);
                ldsm4(aa + T_AH, ah[i][0], ah[i][1], ah[i][2], ah[i][3]);
                ldsm4(aa + T_AL, al[i][0], al[i][1], al[i][2], al[i][3]);
            }
            #pragma unroll
            for (int jp = 0; jp < 4; jp++) {
                uint32_t ba = sgb + boff + kb + (uint32_t)(jp * 16 * PITCH);
                uint32_t bh[4], bl[4];
                ldsm4(ba + T_BH, bh[0], bh[1], bh[2], bh[3]);
                ldsm4(ba + T_BL, bl[0], bl[1], bl[2], bl[3]);
                #pragma unroll
                for (int i = 0; i < 2; i++) {
                    float* c0 = acc[i][2 * jp];
                    float* c1 = acc[i][2 * jp + 1];
                    mma16816(c0, ah[i][0], ah[i][1], ah[i][2], ah[i][3], bh[0], bh[1]);
                    mma16816(c0, al[i][0], al[i][1], al[i][2], al[i][3], bh[0], bh[1]);
                    mma16816(c0, ah[i][0], ah[i][1], ah[i][2], ah[i][3], bl[0], bl[1]);
                    mma16816(c1, ah[i][0], ah[i][1], ah[i][2], ah[i][3], bh[2], bh[3]);
                    mma16816(c1, al[i][0], al[i][1], al[i][2], al[i][3], bh[2], bh[3]);
                    mma16816(c1, ah[i][0], ah[i][1], ah[i][2], ah[i][3], bl[2], bl[3]);
                }
            }
        }
        __syncthreads();
    }

    // epilogue: bias + convert to fp16, store g_ch
    int g = lane >> 2, t4 = lane & 3;
    #pragma unroll
    for (int i = 0; i < 2; i++) {
        int row0 = m0 + warp_m * 32 + i * 16 + g;
        #pragma unroll
        for (int j = 0; j < 8; j++) {
            int col = n0 + warp_n * 64 + j * 8 + 2 * t4;
            float cb0 = g_cb[col], cb1 = g_cb[col + 1];
            if (row0 < N) {
                __half2 h = __floats2half2_rn(acc[i][j][0] + cb0, acc[i][j][1] + cb1);
                *(__half2*)(g_ch + (size_t)row0 * HIDDEN + col) = h;
            }
            if (row0 + 8 < N) {
                __half2 h = __floats2half2_rn(acc[i][j][2] + cb0, acc[i][j][3] + cb1);
                *(__half2*)(g_ch + (size_t)(row0 + 8) * HIDDEN + col) = h;
            }
        }
    }
}

// ---------------- CSR build ----------------
__global__ void k_zero(int N) {
    int i = blockIdx.x * blockDim.x + threadIdx.x;
    if (i < N) g_counts[i] = 0;
}

__global__ void k_hist(const void* __restrict__ rowp, int E) {
    int e = blockIdx.x * blockDim.x + threadIdx.x;
    if (e >= E) return;
    int r = g_is64 ? (int)((const long long*)rowp)[e] : ((const int*)rowp)[e];
    atomicAdd(&g_counts[r], 1);
}

// coalesced 3-phase scan
__global__ void k_bsum(int N) {
    __shared__ int sh[256];
    int t = threadIdx.x;
    int i = blockIdx.x * 256 + t;
    sh[t] = (i < N) ? g_counts[i] : 0;
    __syncthreads();
    #pragma unroll
    for (int o = 128; o > 0; o >>= 1) {
        if (t < o) sh[t] += sh[t + o];
        __syncthreads();
    }
    if (t == 0) g_bsum[blockIdx.x] = sh[0];
}

__global__ void k_bscan(int nb) {
    __shared__ int sh[512];
    int t = threadIdx.x;
    int v = (t < nb) ? g_bsum[t] : 0;
    sh[t] = v;
    __syncthreads();
    int acc = v;
    #pragma unroll
    for (int o = 1; o < 512; o <<= 1) {
        int u = (t >= o) ? sh[t - o] : 0;
        __syncthreads();
        acc += u;
        sh[t] = acc;
        __syncthreads();
    }
    if (t < nb) g_boff[t] = acc - v;   // exclusive
}

__global__ void k_rows(int N) {
    __shared__ int sh[256];
    int t = threadIdx.x;
    int i = blockIdx.x * 256 + t;
    int v = (i < N) ? g_counts[i] : 0;
    sh[t] = v;
    __syncthreads();
    int acc = v;
    #pragma unroll
    for (int o = 1; o < 256; o <<= 1) {
        int u = (t >= o) ? sh[t - o] : 0;
        __syncthreads();
        acc += u;
        sh[t] = acc;
        __syncthreads();
    }
    if (i < N) {
        int start = g_boff[blockIdx.x] + acc - v;
        g_rowstart[i] = start;
        g_cursor[i]   = start;
    }
}

// ---------------- scatter + fused per-edge softmax weight ----------------
__global__ void k_scatter(const void* __restrict__ rowp,
                          const void* __restrict__ colp,
                          const float* __restrict__ asg_b1,
                          const float* __restrict__ asg_W2,
                          const float* __restrict__ asg_b2, int E) {
    int e = blockIdx.x * blockDim.x + threadIdx.x;
    if (e >= E) return;
    int r, c;
    if (g_is64) {
        r = (int)((const long long*)rowp)[e];
        c = (int)((const long long*)colp)[e];
    } else {
        r = ((const int*)rowp)[e];
        c = ((const int*)colp)[e];
    }
    int pos = atomicAdd(&g_cursor[r], 1);
    g_csrcol[pos] = c;

    float4 pav = __ldg((const float4*)(g_proj + (size_t)c * 8));
    float4 pbv = __ldg((const float4*)(g_proj + (size_t)r * 8 + 4));
    float h1[4] = {pav.x + pbv.x + __ldg(asg_b1 + 0),
                   pav.y + pbv.y + __ldg(asg_b1 + 1),
                   pav.z + pbv.z + __ldg(asg_b1 + 2),
                   pav.w + pbv.w + __ldg(asg_b1 + 3)};
    float h2[4], mx = -1e30f;
    #pragma unroll
    for (int k = 0; k < 4; k++) {
        float s = __ldg(asg_b2 + k);
        #pragma unroll
        for (int d = 0; d < 4; d++) s = fmaf(h1[d], __ldg(asg_W2 + k * 4 + d), s);
        h2[k] = s; mx = fmaxf(mx, s);
    }
    float e0 = __expf(h2[0]-mx), e1 = __expf(h2[1]-mx);
    float e2 = __expf(h2[2]-mx), e3 = __expf(h2[3]-mx);
    float inv = 1.f / (e0+e1+e2+e3);
    g_w[pos] = make_float4(e0*inv, e1*inv, e2*inv, e3*inv);
}

// ---------------- fused aggregate + bias + norm + classifier ----------------
// one warp per row; weights precomputed; c gathered as fp16 (16B/lane/edge)
__global__ __launch_bounds__(256)
void k_agg(const float* __restrict__ bias,
           const float* __restrict__ cls_W, const float* __restrict__ cls_b,
           float* __restrict__ hout, float* __restrict__ logits, int N) {
    __shared__ float sw[8][32][4];
    __shared__ int   sc[8][32];

    int wid  = threadIdx.x >> 5;
    int lane = threadIdx.x & 31;
    int r    = blockIdx.x * 8 + wid;
    if (r >= N) return;

    int start = g_rowstart[r];
    int deg   = g_counts[r];
    int myg   = lane >> 3;

    float a[8];
    #pragma unroll
    for (int t = 0; t < 8; t++) a[t] = 0.f;

    for (int base = 0; base < deg; base += 32) {
        int cnt = deg - base; if (cnt > 32) cnt = 32;
        if (lane < cnt) {
            int idx = start + base + lane;
            sc[wid][lane] = g_csrcol[idx];
            float4 wv = __ldg(g_w + idx);
            sw[wid][lane][0] = wv.x; sw[wid][lane][1] = wv.y;
            sw[wid][lane][2] = wv.z; sw[wid][lane][3] = wv.w;
        }
        __syncwarp();

        #pragma unroll 8
        for (int j = 0; j < cnt; j++) {
            int   cj = sc[wid][j];
            float wj = sw[wid][j][myg];
            uint4 hv = __ldg((const uint4*)(g_ch + (size_t)cj * HIDDEN) + lane);
            float2 f0 = __half22float2(*(__half2*)&hv.x);
            float2 f1 = __half22float2(*(__half2*)&hv.y);
            float2 f2 = __half22float2(*(__half2*)&hv.z);
            float2 f3 = __half22float2(*(__half2*)&hv.w);
            a[0] = fmaf(f0.x, wj, a[0]); a[1] = fmaf(f0.y, wj, a[1]);
            a[2] = fmaf(f1.x, wj, a[2]); a[3] = fmaf(f1.y, wj, a[3]);
            a[4] = fmaf(f2.x, wj, a[4]); a[5] = fmaf(f2.y, wj, a[5]);
            a[6] = fmaf(f3.x, wj, a[6]); a[7] = fmaf(f3.y, wj, a[7]);
        }
        __syncwarp();
    }

    float4 bb0 = __ldg((const float4*)bias + lane * 2);
    float4 bb1 = __ldg((const float4*)bias + lane * 2 + 1);
    a[0] += bb0.x; a[1] += bb0.y; a[2] += bb0.z; a[3] += bb0.w;
    a[4] += bb1.x; a[5] += bb1.y; a[6] += bb1.z; a[7] += bb1.w;

    float ss = 0.f;
    #pragma unroll
    for (int t = 0; t < 8; t++) ss = fmaf(a[t], a[t], ss);
    #pragma unroll
    for (int o = 1; o < 8; o <<= 1)
        ss += __shfl_xor_sync(0xFFFFFFFFu, ss, o);
    float invn = 1.f / fmaxf(sqrtf(ss), 1e-12f);
    #pragma unroll
    for (int t = 0; t < 8; t++) a[t] *= invn;

    float4* hr = (float4*)(hout + (size_t)r * HIDDEN) + lane * 2;
    hr[0] = make_float4(a[0], a[1], a[2], a[3]);
    hr[1] = make_float4(a[4], a[5], a[6], a[7]);

    float lp[4];
    #pragma unroll
    for (int cc = 0; cc < 4; cc++) {
        const float4* cwp = (const float4*)(cls_W + cc * HIDDEN) + lane * 2;
        float4 c0 = __ldg(cwp), c1 = __ldg(cwp + 1);
        lp[cc] = a[0]*c0.x + a[1]*c0.y + a[2]*c0.z + a[3]*c0.w
               + a[4]*c1.x + a[5]*c1.y + a[6]*c1.z + a[7]*c1.w;
    }
    #pragma unroll
    for (int cc = 0; cc < 4; cc++)
        #pragma unroll
        for (int o = 16; o > 0; o >>= 1)
            lp[cc] += __shfl_xor_sync(0xFFFFFFFFu, lp[cc], o);
    if (lane == 0) {
        #pragma unroll
        for (int cc = 0; cc < 4; cc++)
            logits[(size_t)r * NCLASS + cc] = lp[cc] + __ldg(cls_b + cc);
    }
}

// ---------------- launch ----------------
extern "C" void kernel_launch(void* const* d_in, const int* in_sizes, int n_in,
                              void* d_out, int out_size) {
    const float* x      = (const float*)d_in[0];
    const void*  rowp   = d_in[1];
    const void*  colp   = d_in[2];
    const float* asg_W1 = (const float*)d_in[3];
    const float* asg_b1 = (const float*)d_in[4];
    const float* asg_W2 = (const float*)d_in[5];
    const float* asg_b2 = (const float*)d_in[6];
    const float* lin_W  = (const float*)d_in[7];
    const float* lin_b  = (const float*)d_in[8];
    const float* conv_W = (const float*)d_in[9];
    const float* bias   = (const float*)d_in[10];
    const float* cls_W  = (const float*)d_in[11];
    const float* cls_b  = (const float*)d_in[12];

    int N = in_sizes[0] / NFEAT;
    int E = in_sizes[1];
    int nb = (N + 255) / 256;

    float* hout   = (float*)d_out;
    float* logits = hout + (size_t)N * HIDDEN;

    cudaFuncSetAttribute(k_cmma, cudaFuncAttributeMaxDynamicSharedMemorySize,
                         SM_DYN);

    k_detect<<<1, 32>>>((const unsigned int*)rowp, E);
    k_fold<<<HIDDEN, NFEAT>>>(conv_W, lin_W, lin_b);
    k_proj<<<(N + 7) / 8, 256>>>(x, asg_W1, N);
    dim3 gg((N + 127) / 128, HIDDEN / 128);
    k_cmma<<<gg, 256, SM_DYN>>>(N);
    k_zero<<<(N + 255) / 256, 256>>>(N);
    k_hist<<<(E + 255) / 256, 256>>>(rowp, E);
    k_bsum<<<nb, 256>>>(N);
    k_bscan<<<1, 512>>>(nb);
    k_rows<<<nb, 256>>>(N);
    k_scatter<<<(E + 255) / 256, 256>>>(rowp, colp, asg_b1, asg_W2, asg_b2, E);
    k_agg<<<(N + 7) / 8, 256>>>(bias, cls_W, cls_b, hout, logits, N);
}

// round 15
// speedup vs baseline: 1.7619x; 1.1203x over previous
#include <cuda_runtime.h>
#include <cuda_fp16.h>
#include <math.h>
#include <cstdint>

#define NFEAT   256
#define HIDDEN  256
#define PCH     64
#define NCLASS  4
#define MAXN    100000
#define MAXE    1600000

typedef unsigned long long ull;

__device__ __forceinline__ uint32_t smem_u32(const void* p) {
    uint32_t a;
    asm("{ .reg .u64 t; cvta.to.shared.u64 t, %1; cvt.u32.u64 %0, t; }"
        : "=r"(a) : "l"(p));
    return a;
}
__device__ __forceinline__ void ldsm4(uint32_t addr, uint32_t& r0, uint32_t& r1,
                                      uint32_t& r2, uint32_t& r3) {
    asm volatile("ldmatrix.sync.aligned.m8n8.x4.shared.b16 {%0,%1,%2,%3}, [%4];"
                 : "=r"(r0), "=r"(r1), "=r"(r2), "=r"(r3) : "r"(addr));
}
__device__ __forceinline__ void mma16816h(float* c, uint32_t a0, uint32_t a1,
                                          uint32_t a2, uint32_t a3,
                                          uint32_t b0, uint32_t b1) {
    asm volatile(
        "mma.sync.aligned.m16n8k16.row.col.f32.f16.f16.f32 "
        "{%0,%1,%2,%3}, {%4,%5,%6,%7}, {%8,%9}, {%0,%1,%2,%3};"
        : "+f"(c[0]), "+f"(c[1]), "+f"(c[2]), "+f"(c[3])
        : "r"(a0), "r"(a1), "r"(a2), "r"(a3), "r"(b0), "r"(b1));
}
__device__ __forceinline__ void cp16z(uint32_t dst, const void* src, int inb) {
    int sz = inb ? 16 : 0;
    asm volatile("cp.async.cg.shared.global [%0], [%1], 16, %2;"
                 :: "r"(dst), "l"(src), "r"(sz));
}
__device__ __forceinline__ void cp16(uint32_t dst, const void* src) {
    asm volatile("cp.async.cg.shared.global [%0], [%1], 16;"
                 :: "r"(dst), "l"(src));
}

// ---------------- device scratch ----------------
__device__ int   g_is64;
__device__ float g_cb[HIDDEN];
__device__ float g_proj[MAXN * 8];
__device__ __half g_ch[(size_t)MAXN * HIDDEN];      // fp16 message matrix
__device__ __half g_xh[(size_t)MAXN * NFEAT];       // fp16 x
__device__ __half g_cwh[HIDDEN * NFEAT];            // fp16 CW hi
__device__ __half g_cwl[HIDDEN * NFEAT];            // fp16 CW lo
__device__ int   g_counts[MAXN];
__device__ int   g_rowstart[MAXN];
__device__ int   g_cursor[MAXN];
__device__ int   g_csrcol[MAXE];
__device__ float4 g_w[MAXE];
__device__ int   g_bsum[512];
__device__ int   g_boff[512];

// ---------------- index width sniffing ----------------
__global__ void k_detect(const unsigned int* __restrict__ rowp, int E) {
    if (threadIdx.x == 0 && blockIdx.x == 0) {
        int n = E < 64 ? E : 64;
        int all_hi_zero = 1;
        for (int i = 0; i < n; i++)
            if (rowp[2 * i + 1] != 0u) { all_hi_zero = 0; break; }
        g_is64 = all_hi_zero;
    }
}

// ---------------- fold conv into lin, output fp16 hi/lo ----------------
__global__ void k_fold(const float* __restrict__ conv_W,
                       const float* __restrict__ lin_W,
                       const float* __restrict__ lin_b) {
    int t = blockIdx.x, f = threadIdx.x;
    int k = t >> 6, q = t & 63;
    const float* cw = conv_W + (k * PCH + q) * PCH;
    const float* lw = lin_W + (size_t)k * PCH * NFEAT;
    float s = 0.f;
    #pragma unroll 8
    for (int p = 0; p < PCH; p++) s = fmaf(cw[p], lw[p * NFEAT + f], s);
    __half hi = __float2half(s);
    g_cwh[t * NFEAT + f] = hi;
    g_cwl[t * NFEAT + f] = __float2half(s - __half2float(hi));
    if (f == 0) {
        const float* lb = lin_b + k * PCH;
        float b = 0.f;
        for (int p = 0; p < PCH; p++) b = fmaf(cw[p], lb[p], b);
        g_cb[t] = b;
    }
}

// ---------------- projections + x -> fp16 (single x read) ----------------
__global__ void k_proj(const float* __restrict__ x,
                       const float* __restrict__ asg_W1, int N) {
    int warp = (blockIdx.x * blockDim.x + threadIdx.x) >> 5;
    int lane = threadIdx.x & 31;
    if (warp >= N) return;
    const float* xr = x + (size_t)warp * NFEAT;
    float pa[4] = {0,0,0,0}, pb[4] = {0,0,0,0};
    #pragma unroll
    for (int t = 0; t < 8; t++) {
        int f = lane + 32 * t;
        float xv = xr[f];
        g_xh[(size_t)warp * NFEAT + f] = __float2half(xv);
        #pragma unroll
        for (int c = 0; c < 4; c++) {
            pa[c] = fmaf(xv, asg_W1[c * 512 + f], pa[c]);
            pb[c] = fmaf(xv, asg_W1[c * 512 + 256 + f], pb[c]);
        }
    }
    #pragma unroll
    for (int c = 0; c < 4; c++)
        #pragma unroll
        for (int o = 16; o > 0; o >>= 1) {
            pa[c] += __shfl_xor_sync(0xFFFFFFFFu, pa[c], o);
            pb[c] += __shfl_xor_sync(0xFFFFFFFFu, pb[c], o);
        }
    if (lane == 0) {
        #pragma unroll
        for (int c = 0; c < 4; c++) {
            g_proj[warp * 8 + c]     = pa[c];
            g_proj[warp * 8 + 4 + c] = pb[c];
        }
    }
}

// ---------------- c = X @ CW^T + cb  via mma.sync fp16, 2 terms ----------------
#define CHK 32
#define PITCH 80
#define T_A  0
#define T_BH (128 * PITCH)
#define T_BL (2 * 128 * PITCH)
#define STAGE_BYTES (3 * 128 * PITCH)
#define SM_DYN (2 * STAGE_BYTES)
#define NCHUNK (NFEAT / CHK)

__global__ __launch_bounds__(256, 2)
void k_cmma(int N) {
    extern __shared__ __align__(16) char sm[];
    uint32_t sb = smem_u32(sm);
    int tid  = threadIdx.x;
    int wid  = tid >> 5;
    int lane = tid & 31;
    int m0 = blockIdx.x * 128;
    int n0 = blockIdx.y * 128;
    int warp_m = wid >> 1;
    int warp_n = wid & 1;

    float acc[2][8][4];
    #pragma unroll
    for (int i = 0; i < 2; i++)
        #pragma unroll
        for (int j = 0; j < 8; j++)
            #pragma unroll
            for (int q = 0; q < 4; q++) acc[i][j][q] = 0.f;

    int a_row = warp_m * 32 + (lane & 15);
    int a_col = (lane >> 4) << 3;
    uint32_t aoff = (uint32_t)(a_row * PITCH + a_col * 2);
    int b_row_base = warp_n * 64 + ((lane >> 4) << 3) + (lane & 7);
    int b_col = ((lane >> 3) & 1) << 3;
    uint32_t boff = (uint32_t)(b_row_base * PITCH + b_col * 2);

    int lrow = tid >> 2;
    int lseg = tid & 3;

    auto load_stage = [&](int s, int k0) {
        uint32_t sgb = sb + (uint32_t)(s * STAGE_BYTES);
        #pragma unroll
        for (int ps = 0; ps < 2; ps++) {
            int r = lrow + ps * 64;
            uint32_t dst = sgb + (uint32_t)(r * PITCH + lseg * 16);
            int gm = m0 + r;
            int inb = gm < N;
            const __half* ah = g_xh + (size_t)(inb ? gm : 0) * NFEAT + k0 + lseg * 8;
            cp16z(dst + T_A, ah, inb);
            int gn = n0 + r;
            cp16(dst + T_BH, g_cwh + (size_t)gn * NFEAT + k0 + lseg * 8);
            cp16(dst + T_BL, g_cwl + (size_t)gn * NFEAT + k0 + lseg * 8);
        }
        asm volatile("cp.async.commit_group;");
    };

    load_stage(0, 0);

    #pragma unroll 1
    for (int chunk = 0; chunk < NCHUNK; chunk++) {
        int s = chunk & 1;
        asm volatile("cp.async.wait_group 0;" ::: "memory");
        __syncthreads();
        if (chunk + 1 < NCHUNK) load_stage(s ^ 1, (chunk + 1) * CHK);

        uint32_t sgb = sb + (uint32_t)(s * STAGE_BYTES);
        #pragma unroll
        for (int ka = 0; ka < CHK / 16; ka++) {
            uint32_t kb = (uint32_t)(ka * 16 * 2);
            uint32_t ah[2][4];
            #pragma unroll
            for (int i = 0; i < 2; i++) {
                uint32_t aa = sgb + aoff + kb + (uint32_t)(i * 16 * PITCH);
                ldsm4(aa + T_A, ah[i][0], ah[i][1], ah[i][2], ah[i][3]);
            }
            #pragma unroll
            for (int jp = 0; jp < 4; jp++) {
                uint32_t ba = sgb + boff + kb + (uint32_t)(jp * 16 * PITCH);
                uint32_t bh[4], bl[4];
                ldsm4(ba + T_BH, bh[0], bh[1], bh[2], bh[3]);
                ldsm4(ba + T_BL, bl[0], bl[1], bl[2], bl[3]);
                #pragma unroll
                for (int i = 0; i < 2; i++) {
                    float* c0 = acc[i][2 * jp];
                    float* c1 = acc[i][2 * jp + 1];
                    mma16816h(c0, ah[i][0], ah[i][1], ah[i][2], ah[i][3], bh[0], bh[1]);
                    mma16816h(c0, ah[i][0], ah[i][1], ah[i][2], ah[i][3], bl[0], bl[1]);
                    mma16816h(c1, ah[i][0], ah[i][1], ah[i][2], ah[i][3], bh[2], bh[3]);
                    mma16816h(c1, ah[i][0], ah[i][1], ah[i][2], ah[i][3], bl[2], bl[3]);
                }
            }
        }
        __syncthreads();
    }

    // epilogue: bias + convert to fp16, store g_ch
    int g = lane >> 2, t4 = lane & 3;
    #pragma unroll
    for (int i = 0; i < 2; i++) {
        int row0 = m0 + warp_m * 32 + i * 16 + g;
        #pragma unroll
        for (int j = 0; j < 8; j++) {
            int col = n0 + warp_n * 64 + j * 8 + 2 * t4;
            float cb0 = g_cb[col], cb1 = g_cb[col + 1];
            if (row0 < N) {
                __half2 h = __floats2half2_rn(acc[i][j][0] + cb0, acc[i][j][1] + cb1);
                *(__half2*)(g_ch + (size_t)row0 * HIDDEN + col) = h;
            }
            if (row0 + 8 < N) {
                __half2 h = __floats2half2_rn(acc[i][j][2] + cb0, acc[i][j][3] + cb1);
                *(__half2*)(g_ch + (size_t)(row0 + 8) * HIDDEN + col) = h;
            }
        }
    }
}

// ---------------- CSR build ----------------
__global__ void k_zero(int N) {
    int i = blockIdx.x * blockDim.x + threadIdx.x;
    if (i < N) g_counts[i] = 0;
}

__global__ void k_hist(const void* __restrict__ rowp, int E) {
    int e = blockIdx.x * blockDim.x + threadIdx.x;
    if (e >= E) return;
    int r = g_is64 ? (int)((const long long*)rowp)[e] : ((const int*)rowp)[e];
    atomicAdd(&g_counts[r], 1);
}

// coalesced 3-phase scan
__global__ void k_bsum(int N) {
    __shared__ int sh[256];
    int t = threadIdx.x;
    int i = blockIdx.x * 256 + t;
    sh[t] = (i < N) ? g_counts[i] : 0;
    __syncthreads();
    #pragma unroll
    for (int o = 128; o > 0; o >>= 1) {
        if (t < o) sh[t] += sh[t + o];
        __syncthreads();
    }
    if (t == 0) g_bsum[blockIdx.x] = sh[0];
}

__global__ void k_bscan(int nb) {
    __shared__ int sh[512];
    int t = threadIdx.x;
    int v = (t < nb) ? g_bsum[t] : 0;
    sh[t] = v;
    __syncthreads();
    int acc = v;
    #pragma unroll
    for (int o = 1; o < 512; o <<= 1) {
        int u = (t >= o) ? sh[t - o] : 0;
        __syncthreads();
        acc += u;
        sh[t] = acc;
        __syncthreads();
    }
    if (t < nb) g_boff[t] = acc - v;   // exclusive
}

__global__ void k_rows(int N) {
    __shared__ int sh[256];
    int t = threadIdx.x;
    int i = blockIdx.x * 256 + t;
    int v = (i < N) ? g_counts[i] : 0;
    sh[t] = v;
    __syncthreads();
    int acc = v;
    #pragma unroll
    for (int o = 1; o < 256; o <<= 1) {
        int u = (t >= o) ? sh[t - o] : 0;
        __syncthreads();
        acc += u;
        sh[t] = acc;
        __syncthreads();
    }
    if (i < N) {
        int start = g_boff[blockIdx.x] + acc - v;
        g_rowstart[i] = start;
        g_cursor[i]   = start;
    }
}

// ---------------- scatter + fused per-edge softmax weight ----------------
__global__ void k_scatter(const void* __restrict__ rowp,
                          const void* __restrict__ colp,
                          const float* __restrict__ asg_b1,
                          const float* __restrict__ asg_W2,
                          const float* __restrict__ asg_b2, int E) {
    int e = blockIdx.x * blockDim.x + threadIdx.x;
    if (e >= E) return;
    int r, c;
    if (g_is64) {
        r = (int)((const long long*)rowp)[e];
        c = (int)((const long long*)colp)[e];
    } else {
        r = ((const int*)rowp)[e];
        c = ((const int*)colp)[e];
    }
    int pos = atomicAdd(&g_cursor[r], 1);
    g_csrcol[pos] = c;

    float4 pav = __ldg((const float4*)(g_proj + (size_t)c * 8));
    float4 pbv = __ldg((const float4*)(g_proj + (size_t)r * 8 + 4));
    float h1[4] = {pav.x + pbv.x + __ldg(asg_b1 + 0),
                   pav.y + pbv.y + __ldg(asg_b1 + 1),
                   pav.z + pbv.z + __ldg(asg_b1 + 2),
                   pav.w + pbv.w + __ldg(asg_b1 + 3)};
    float h2[4], mx = -1e30f;
    #pragma unroll
    for (int k = 0; k < 4; k++) {
        float s = __ldg(asg_b2 + k);
        #pragma unroll
        for (int d = 0; d < 4; d++) s = fmaf(h1[d], __ldg(asg_W2 + k * 4 + d), s);
        h2[k] = s; mx = fmaxf(mx, s);
    }
    float e0 = __expf(h2[0]-mx), e1 = __expf(h2[1]-mx);
    float e2 = __expf(h2[2]-mx), e3 = __expf(h2[3]-mx);
    float inv = 1.f / (e0+e1+e2+e3);
    g_w[pos] = make_float4(e0*inv, e1*inv, e2*inv, e3*inv);
}

// ---------------- fused aggregate + bias + norm + classifier ----------------
__global__ __launch_bounds__(256)
void k_agg(const float* __restrict__ bias,
           const float* __restrict__ cls_W, const float* __restrict__ cls_b,
           float* __restrict__ hout, float* __restrict__ logits, int N) {
    __shared__ float sw[8][32][4];
    __shared__ int   sc[8][32];

    int wid  = threadIdx.x >> 5;
    int lane = threadIdx.x & 31;
    int r    = blockIdx.x * 8 + wid;
    if (r >= N) return;

    int start = g_rowstart[r];
    int deg   = g_counts[r];
    int myg   = lane >> 3;

    float a[8];
    #pragma unroll
    for (int t = 0; t < 8; t++) a[t] = 0.f;

    for (int base = 0; base < deg; base += 32) {
        int cnt = deg - base; if (cnt > 32) cnt = 32;
        if (lane < cnt) {
            int idx = start + base + lane;
            sc[wid][lane] = g_csrcol[idx];
            float4 wv = __ldg(g_w + idx);
            sw[wid][lane][0] = wv.x; sw[wid][lane][1] = wv.y;
            sw[wid][lane][2] = wv.z; sw[wid][lane][3] = wv.w;
        }
        __syncwarp();

        #pragma unroll 8
        for (int j = 0; j < cnt; j++) {
            int   cj = sc[wid][j];
            float wj = sw[wid][j][myg];
            uint4 hv = __ldg((const uint4*)(g_ch + (size_t)cj * HIDDEN) + lane);
            float2 f0 = __half22float2(*(__half2*)&hv.x);
            float2 f1 = __half22float2(*(__half2*)&hv.y);
            float2 f2 = __half22float2(*(__half2*)&hv.z);
            float2 f3 = __half22float2(*(__half2*)&hv.w);
            a[0] = fmaf(f0.x, wj, a[0]); a[1] = fmaf(f0.y, wj, a[1]);
            a[2] = fmaf(f1.x, wj, a[2]); a[3] = fmaf(f1.y, wj, a[3]);
            a[4] = fmaf(f2.x, wj, a[4]); a[5] = fmaf(f2.y, wj, a[5]);
            a[6] = fmaf(f3.x, wj, a[6]); a[7] = fmaf(f3.y, wj, a[7]);
        }
        __syncwarp();
    }

    float4 bb0 = __ldg((const float4*)bias + lane * 2);
    float4 bb1 = __ldg((const float4*)bias + lane * 2 + 1);
    a[0] += bb0.x; a[1] += bb0.y; a[2] += bb0.z; a[3] += bb0.w;
    a[4] += bb1.x; a[5] += bb1.y; a[6] += bb1.z; a[7] += bb1.w;

    float ss = 0.f;
    #pragma unroll
    for (int t = 0; t < 8; t++) ss = fmaf(a[t], a[t], ss);
    #pragma unroll
    for (int o = 1; o < 8; o <<= 1)
        ss += __shfl_xor_sync(0xFFFFFFFFu, ss, o);
    float invn = 1.f / fmaxf(sqrtf(ss), 1e-12f);
    #pragma unroll
    for (int t = 0; t < 8; t++) a[t] *= invn;

    float4* hr = (float4*)(hout + (size_t)r * HIDDEN) + lane * 2;
    hr[0] = make_float4(a[0], a[1], a[2], a[3]);
    hr[1] = make_float4(a[4], a[5], a[6], a[7]);

    float lp[4];
    #pragma unroll
    for (int cc = 0; cc < 4; cc++) {
        const float4* cwp = (const float4*)(cls_W + cc * HIDDEN) + lane * 2;
        float4 c0 = __ldg(cwp), c1 = __ldg(cwp + 1);
        lp[cc] = a[0]*c0.x + a[1]*c0.y + a[2]*c0.z + a[3]*c0.w
               + a[4]*c1.x + a[5]*c1.y + a[6]*c1.z + a[7]*c1.w;
    }
    #pragma unroll
    for (int cc = 0; cc < 4; cc++)
        #pragma unroll
        for (int o = 16; o > 0; o >>= 1)
            lp[cc] += __shfl_xor_sync(0xFFFFFFFFu, lp[cc], o);
    if (lane == 0) {
        #pragma unroll
        for (int cc = 0; cc < 4; cc++)
            logits[(size_t)r * NCLASS + cc] = lp[cc] + __ldg(cls_b + cc);
    }
}

// ---------------- launch ----------------
extern "C" void kernel_launch(void* const* d_in, const int* in_sizes, int n_in,
                              void* d_out, int out_size) {
    const float* x      = (const float*)d_in[0];
    const void*  rowp   = d_in[1];
    const void*  colp   = d_in[2];
    const float* asg_W1 = (const float*)d_in[3];
    const float* asg_b1 = (const float*)d_in[4];
    const float* asg_W2 = (const float*)d_in[5];
    const float* asg_b2 = (const float*)d_in[6];
    const float* lin_W  = (const float*)d_in[7];
    const float* lin_b  = (const float*)d_in[8];
    const float* conv_W = (const float*)d_in[9];
    const float* bias   = (const float*)d_in[10];
    const float* cls_W  = (const float*)d_in[11];
    const float* cls_b  = (const float*)d_in[12];

    int N = in_sizes[0] / NFEAT;
    int E = in_sizes[1];
    int nb = (N + 255) / 256;

    float* hout   = (float*)d_out;
    float* logits = hout + (size_t)N * HIDDEN;

    cudaFuncSetAttribute(k_cmma, cudaFuncAttributeMaxDynamicSharedMemorySize,
                         SM_DYN);

    k_detect<<<1, 32>>>((const unsigned int*)rowp, E);
    k_fold<<<HIDDEN, NFEAT>>>(conv_W, lin_W, lin_b);
    k_proj<<<(N + 7) / 8, 256>>>(x, asg_W1, N);
    dim3 gg((N + 127) / 128, HIDDEN / 128);
    k_cmma<<<gg, 256, SM_DYN>>>(N);
    k_zero<<<(N + 255) / 256, 256>>>(N);
    k_hist<<<(E + 255) / 256, 256>>>(rowp, E);
    k_bsum<<<nb, 256>>>(N);
    k_bscan<<<1, 512>>>(nb);
    k_rows<<<nb, 256>>>(N);
    k_scatter<<<(E + 255) / 256, 256>>>(rowp, colp, asg_b1, asg_W2, asg_b2, E);
    k_agg<<<(N + 7) / 8, 256>>>(bias, cls_W, cls_b, hout, logits, N);
}

// round 16
// speedup vs baseline: 1.9114x; 1.0849x over previous
#include <cuda_runtime.h>
#include <cuda_fp16.h>
#include <math.h>
#include <cstdint>

#define NFEAT   256
#define HIDDEN  256
#define PCH     64
#define NCLASS  4
#define MAXN    100000
#define MAXE    1600000

typedef unsigned long long ull;

__device__ __forceinline__ uint32_t smem_u32(const void* p) {
    uint32_t a;
    asm("{ .reg .u64 t; cvta.to.shared.u64 t, %1; cvt.u32.u64 %0, t; }"
        : "=r"(a) : "l"(p));
    return a;
}
__device__ __forceinline__ void ldsm4(uint32_t addr, uint32_t& r0, uint32_t& r1,
                                      uint32_t& r2, uint32_t& r3) {
    asm volatile("ldmatrix.sync.aligned.m8n8.x4.shared.b16 {%0,%1,%2,%3}, [%4];"
                 : "=r"(r0), "=r"(r1), "=r"(r2), "=r"(r3) : "r"(addr));
}
__device__ __forceinline__ void mma16816h(float* c, uint32_t a0, uint32_t a1,
                                          uint32_t a2, uint32_t a3,
                                          uint32_t b0, uint32_t b1) {
    asm volatile(
        "mma.sync.aligned.m16n8k16.row.col.f32.f16.f16.f32 "
        "{%0,%1,%2,%3}, {%4,%5,%6,%7}, {%8,%9}, {%0,%1,%2,%3};"
        : "+f"(c[0]), "+f"(c[1]), "+f"(c[2]), "+f"(c[3])
        : "r"(a0), "r"(a1), "r"(a2), "r"(a3), "r"(b0), "r"(b1));
}
__device__ __forceinline__ void cp16z(uint32_t dst, const void* src, int inb) {
    int sz = inb ? 16 : 0;
    asm volatile("cp.async.cg.shared.global [%0], [%1], 16, %2;"
                 :: "r"(dst), "l"(src), "r"(sz));
}
__device__ __forceinline__ void cp16(uint32_t dst, const void* src) {
    asm volatile("cp.async.cg.shared.global [%0], [%1], 16;"
                 :: "r"(dst), "l"(src));
}

// ---------------- device scratch ----------------
__device__ int   g_is64;
__device__ float g_cb[HIDDEN];
__device__ float g_proj[MAXN * 8];
__device__ __half g_ch[(size_t)MAXN * HIDDEN];      // fp16 message matrix
__device__ __half g_xh[(size_t)MAXN * NFEAT];       // fp16 x
__device__ __half g_cwh[HIDDEN * NFEAT];            // fp16 CW
__device__ int   g_counts[MAXN];
__device__ int   g_rowstart[MAXN];
__device__ int   g_cursor[MAXN];
__device__ int   g_csrcol[MAXE];
__device__ float4 g_w[MAXE];
__device__ int   g_bsum[512];
__device__ int   g_boff[512];

// ---------------- index width sniffing ----------------
__global__ void k_detect(const unsigned int* __restrict__ rowp, int E) {
    if (threadIdx.x == 0 && blockIdx.x == 0) {
        int n = E < 64 ? E : 64;
        int all_hi_zero = 1;
        for (int i = 0; i < n; i++)
            if (rowp[2 * i + 1] != 0u) { all_hi_zero = 0; break; }
        g_is64 = all_hi_zero;
    }
}

// ---------------- fold conv into lin, output fp16 ----------------
__global__ void k_fold(const float* __restrict__ conv_W,
                       const float* __restrict__ lin_W,
                       const float* __restrict__ lin_b) {
    int t = blockIdx.x, f = threadIdx.x;
    int k = t >> 6, q = t & 63;
    const float* cw = conv_W + (k * PCH + q) * PCH;
    const float* lw = lin_W + (size_t)k * PCH * NFEAT;
    float s = 0.f;
    #pragma unroll 8
    for (int p = 0; p < PCH; p++) s = fmaf(cw[p], lw[p * NFEAT + f], s);
    g_cwh[t * NFEAT + f] = __float2half(s);
    if (f == 0) {
        const float* lb = lin_b + k * PCH;
        float b = 0.f;
        for (int p = 0; p < PCH; p++) b = fmaf(cw[p], lb[p], b);
        g_cb[t] = b;
    }
}

// ---------------- projections + x -> fp16 (single x read) ----------------
__global__ void k_proj(const float* __restrict__ x,
                       const float* __restrict__ asg_W1, int N) {
    int warp = (blockIdx.x * blockDim.x + threadIdx.x) >> 5;
    int lane = threadIdx.x & 31;
    if (warp >= N) return;
    const float* xr = x + (size_t)warp * NFEAT;
    float pa[4] = {0,0,0,0}, pb[4] = {0,0,0,0};
    #pragma unroll
    for (int t = 0; t < 8; t++) {
        int f = lane + 32 * t;
        float xv = xr[f];
        g_xh[(size_t)warp * NFEAT + f] = __float2half(xv);
        #pragma unroll
        for (int c = 0; c < 4; c++) {
            pa[c] = fmaf(xv, asg_W1[c * 512 + f], pa[c]);
            pb[c] = fmaf(xv, asg_W1[c * 512 + 256 + f], pb[c]);
        }
    }
    #pragma unroll
    for (int c = 0; c < 4; c++)
        #pragma unroll
        for (int o = 16; o > 0; o >>= 1) {
            pa[c] += __shfl_xor_sync(0xFFFFFFFFu, pa[c], o);
            pb[c] += __shfl_xor_sync(0xFFFFFFFFu, pb[c], o);
        }
    if (lane == 0) {
        #pragma unroll
        for (int c = 0; c < 4; c++) {
            g_proj[warp * 8 + c]     = pa[c];
            g_proj[warp * 8 + 4 + c] = pb[c];
        }
    }
}

// ---------------- c = X @ CW^T + cb  via mma.sync fp16, 1 term ----------------
#define CHK 32
#define PITCH 80
#define T_A  0
#define T_B  (128 * PITCH)
#define STAGE_BYTES (2 * 128 * PITCH)
#define SM_DYN (2 * STAGE_BYTES)
#define NCHUNK (NFEAT / CHK)

__global__ __launch_bounds__(256, 2)
void k_cmma(int N) {
    extern __shared__ __align__(16) char sm[];
    uint32_t sb = smem_u32(sm);
    int tid  = threadIdx.x;
    int wid  = tid >> 5;
    int lane = tid & 31;
    int m0 = blockIdx.x * 128;
    int n0 = blockIdx.y * 128;
    int warp_m = wid >> 1;
    int warp_n = wid & 1;

    float acc[2][8][4];
    #pragma unroll
    for (int i = 0; i < 2; i++)
        #pragma unroll
        for (int j = 0; j < 8; j++)
            #pragma unroll
            for (int q = 0; q < 4; q++) acc[i][j][q] = 0.f;

    int a_row = warp_m * 32 + (lane & 15);
    int a_col = (lane >> 4) << 3;
    uint32_t aoff = (uint32_t)(a_row * PITCH + a_col * 2);
    int b_row_base = warp_n * 64 + ((lane >> 4) << 3) + (lane & 7);
    int b_col = ((lane >> 3) & 1) << 3;
    uint32_t boff = (uint32_t)(b_row_base * PITCH + b_col * 2);

    int lrow = tid >> 2;
    int lseg = tid & 3;

    auto load_stage = [&](int s, int k0) {
        uint32_t sgb = sb + (uint32_t)(s * STAGE_BYTES);
        #pragma unroll
        for (int ps = 0; ps < 2; ps++) {
            int r = lrow + ps * 64;
            uint32_t dst = sgb + (uint32_t)(r * PITCH + lseg * 16);
            int gm = m0 + r;
            int inb = gm < N;
            const __half* ah = g_xh + (size_t)(inb ? gm : 0) * NFEAT + k0 + lseg * 8;
            cp16z(dst + T_A, ah, inb);
            int gn = n0 + r;
            cp16(dst + T_B, g_cwh + (size_t)gn * NFEAT + k0 + lseg * 8);
        }
        asm volatile("cp.async.commit_group;");
    };

    load_stage(0, 0);

    #pragma unroll 1
    for (int chunk = 0; chunk < NCHUNK; chunk++) {
        int s = chunk & 1;
        asm volatile("cp.async.wait_group 0;" ::: "memory");
        __syncthreads();
        if (chunk + 1 < NCHUNK) load_stage(s ^ 1, (chunk + 1) * CHK);

        uint32_t sgb = sb + (uint32_t)(s * STAGE_BYTES);
        #pragma unroll
        for (int ka = 0; ka < CHK / 16; ka++) {
            uint32_t kb = (uint32_t)(ka * 16 * 2);
            uint32_t ah[2][4];
            #pragma unroll
            for (int i = 0; i < 2; i++) {
                uint32_t aa = sgb + aoff + kb + (uint32_t)(i * 16 * PITCH);
                ldsm4(aa + T_A, ah[i][0], ah[i][1], ah[i][2], ah[i][3]);
            }
            #pragma unroll
            for (int jp = 0; jp < 4; jp++) {
                uint32_t ba = sgb + boff + kb + (uint32_t)(jp * 16 * PITCH);
                uint32_t bh[4];
                ldsm4(ba + T_B, bh[0], bh[1], bh[2], bh[3]);
                #pragma unroll
                for (int i = 0; i < 2; i++) {
                    mma16816h(acc[i][2 * jp],     ah[i][0], ah[i][1], ah[i][2], ah[i][3], bh[0], bh[1]);
                    mma16816h(acc[i][2 * jp + 1], ah[i][0], ah[i][1], ah[i][2], ah[i][3], bh[2], bh[3]);
                }
            }
        }
        __syncthreads();
    }

    // epilogue: bias + convert to fp16, store g_ch
    int g = lane >> 2, t4 = lane & 3;
    #pragma unroll
    for (int i = 0; i < 2; i++) {
        int row0 = m0 + warp_m * 32 + i * 16 + g;
        #pragma unroll
        for (int j = 0; j < 8; j++) {
            int col = n0 + warp_n * 64 + j * 8 + 2 * t4;
            float cb0 = g_cb[col], cb1 = g_cb[col + 1];
            if (row0 < N) {
                __half2 h = __floats2half2_rn(acc[i][j][0] + cb0, acc[i][j][1] + cb1);
                *(__half2*)(g_ch + (size_t)row0 * HIDDEN + col) = h;
            }
            if (row0 + 8 < N) {
                __half2 h = __floats2half2_rn(acc[i][j][2] + cb0, acc[i][j][3] + cb1);
                *(__half2*)(g_ch + (size_t)(row0 + 8) * HIDDEN + col) = h;
            }
        }
    }
}

// ---------------- CSR build ----------------
__global__ void k_zero(int N) {
    int i = blockIdx.x * blockDim.x + threadIdx.x;
    if (i < N) g_counts[i] = 0;
}

__global__ void k_hist(const void* __restrict__ rowp, int E) {
    int e = blockIdx.x * blockDim.x + threadIdx.x;
    if (e >= E) return;
    int r = g_is64 ? (int)((const long long*)rowp)[e] : ((const int*)rowp)[e];
    atomicAdd(&g_counts[r], 1);
}

// coalesced 3-phase scan
__global__ void k_bsum(int N) {
    __shared__ int sh[256];
    int t = threadIdx.x;
    int i = blockIdx.x * 256 + t;
    sh[t] = (i < N) ? g_counts[i] : 0;
    __syncthreads();
    #pragma unroll
    for (int o = 128; o > 0; o >>= 1) {
        if (t < o) sh[t] += sh[t + o];
        __syncthreads();
    }
    if (t == 0) g_bsum[blockIdx.x] = sh[0];
}

__global__ void k_bscan(int nb) {
    __shared__ int sh[512];
    int t = threadIdx.x;
    int v = (t < nb) ? g_bsum[t] : 0;
    sh[t] = v;
    __syncthreads();
    int acc = v;
    #pragma unroll
    for (int o = 1; o < 512; o <<= 1) {
        int u = (t >= o) ? sh[t - o] : 0;
        __syncthreads();
        acc += u;
        sh[t] = acc;
        __syncthreads();
    }
    if (t < nb) g_boff[t] = acc - v;   // exclusive
}

__global__ void k_rows(int N) {
    __shared__ int sh[256];
    int t = threadIdx.x;
    int i = blockIdx.x * 256 + t;
    int v = (i < N) ? g_counts[i] : 0;
    sh[t] = v;
    __syncthreads();
    int acc = v;
    #pragma unroll
    for (int o = 1; o < 256; o <<= 1) {
        int u = (t >= o) ? sh[t - o] : 0;
        __syncthreads();
        acc += u;
        sh[t] = acc;
        __syncthreads();
    }
    if (i < N) {
        int start = g_boff[blockIdx.x] + acc - v;
        g_rowstart[i] = start;
        g_cursor[i]   = start;
    }
}

// ---------------- scatter + fused per-edge softmax weight ----------------
__global__ void k_scatter(const void* __restrict__ rowp,
                          const void* __restrict__ colp,
                          const float* __restrict__ asg_b1,
                          const float* __restrict__ asg_W2,
                          const float* __restrict__ asg_b2, int E) {
    int e = blockIdx.x * blockDim.x + threadIdx.x;
    if (e >= E) return;
    int r, c;
    if (g_is64) {
        r = (int)((const long long*)rowp)[e];
        c = (int)((const long long*)colp)[e];
    } else {
        r = ((const int*)rowp)[e];
        c = ((const int*)colp)[e];
    }
    int pos = atomicAdd(&g_cursor[r], 1);
    g_csrcol[pos] = c;

    float4 pav = __ldg((const float4*)(g_proj + (size_t)c * 8));
    float4 pbv = __ldg((const float4*)(g_proj + (size_t)r * 8 + 4));
    float h1[4] = {pav.x + pbv.x + __ldg(asg_b1 + 0),
                   pav.y + pbv.y + __ldg(asg_b1 + 1),
                   pav.z + pbv.z + __ldg(asg_b1 + 2),
                   pav.w + pbv.w + __ldg(asg_b1 + 3)};
    float h2[4], mx = -1e30f;
    #pragma unroll
    for (int k = 0; k < 4; k++) {
        float s = __ldg(asg_b2 + k);
        #pragma unroll
        for (int d = 0; d < 4; d++) s = fmaf(h1[d], __ldg(asg_W2 + k * 4 + d), s);
        h2[k] = s; mx = fmaxf(mx, s);
    }
    float e0 = __expf(h2[0]-mx), e1 = __expf(h2[1]-mx);
    float e2 = __expf(h2[2]-mx), e3 = __expf(h2[3]-mx);
    float inv = 1.f / (e0+e1+e2+e3);
    g_w[pos] = make_float4(e0*inv, e1*inv, e2*inv, e3*inv);
}

// ---------------- fused aggregate + bias + norm + classifier ----------------
__global__ __launch_bounds__(256)
void k_agg(const float* __restrict__ bias,
           const float* __restrict__ cls_W, const float* __restrict__ cls_b,
           float* __restrict__ hout, float* __restrict__ logits, int N) {
    __shared__ float sw[8][32][4];
    __shared__ int   sc[8][32];

    int wid  = threadIdx.x >> 5;
    int lane = threadIdx.x & 31;
    int r    = blockIdx.x * 8 + wid;
    if (r >= N) return;

    int start = g_rowstart[r];
    int deg   = g_counts[r];
    int myg   = lane >> 3;

    float a[8];
    #pragma unroll
    for (int t = 0; t < 8; t++) a[t] = 0.f;

    for (int base = 0; base < deg; base += 32) {
        int cnt = deg - base; if (cnt > 32) cnt = 32;
        if (lane < cnt) {
            int idx = start + base + lane;
            sc[wid][lane] = g_csrcol[idx];
            float4 wv = __ldg(g_w + idx);
            sw[wid][lane][0] = wv.x; sw[wid][lane][1] = wv.y;
            sw[wid][lane][2] = wv.z; sw[wid][lane][3] = wv.w;
        }
        __syncwarp();

        #pragma unroll 8
        for (int j = 0; j < cnt; j++) {
            int   cj = sc[wid][j];
            float wj = sw[wid][j][myg];
            uint4 hv = __ldg((const uint4*)(g_ch + (size_t)cj * HIDDEN) + lane);
            float2 f0 = __half22float2(*(__half2*)&hv.x);
            float2 f1 = __half22float2(*(__half2*)&hv.y);
            float2 f2 = __half22float2(*(__half2*)&hv.z);
            float2 f3 = __half22float2(*(__half2*)&hv.w);
            a[0] = fmaf(f0.x, wj, a[0]); a[1] = fmaf(f0.y, wj, a[1]);
            a[2] = fmaf(f1.x, wj, a[2]); a[3] = fmaf(f1.y, wj, a[3]);
            a[4] = fmaf(f2.x, wj, a[4]); a[5] = fmaf(f2.y, wj, a[5]);
            a[6] = fmaf(f3.x, wj, a[6]); a[7] = fmaf(f3.y, wj, a[7]);
        }
        __syncwarp();
    }

    float4 bb0 = __ldg((const float4*)bias + lane * 2);
    float4 bb1 = __ldg((const float4*)bias + lane * 2 + 1);
    a[0] += bb0.x; a[1] += bb0.y; a[2] += bb0.z; a[3] += bb0.w;
    a[4] += bb1.x; a[5] += bb1.y; a[6] += bb1.z; a[7] += bb1.w;

    float ss = 0.f;
    #pragma unroll
    for (int t = 0; t < 8; t++) ss = fmaf(a[t], a[t], ss);
    #pragma unroll
    for (int o = 1; o < 8; o <<= 1)
        ss += __shfl_xor_sync(0xFFFFFFFFu, ss, o);
    float invn = 1.f / fmaxf(sqrtf(ss), 1e-12f);
    #pragma unroll
    for (int t = 0; t < 8; t++) a[t] *= invn;

    float4* hr = (float4*)(hout + (size_t)r * HIDDEN) + lane * 2;
    hr[0] = make_float4(a[0], a[1], a[2], a[3]);
    hr[1] = make_float4(a[4], a[5], a[6], a[7]);

    float lp[4];
    #pragma unroll
    for (int cc = 0; cc < 4; cc++) {
        const float4* cwp = (const float4*)(cls_W + cc * HIDDEN) + lane * 2;
        float4 c0 = __ldg(cwp), c1 = __ldg(cwp + 1);
        lp[cc] = a[0]*c0.x + a[1]*c0.y + a[2]*c0.z + a[3]*c0.w
               + a[4]*c1.x + a[5]*c1.y + a[6]*c1.z + a[7]*c1.w;
    }
    #pragma unroll
    for (int cc = 0; cc < 4; cc++)
        #pragma unroll
        for (int o = 16; o > 0; o >>= 1)
            lp[cc] += __shfl_xor_sync(0xFFFFFFFFu, lp[cc], o);
    if (lane == 0) {
        #pragma unroll
        for (int cc = 0; cc < 4; cc++)
            logits[(size_t)r * NCLASS + cc] = lp[cc] + __ldg(cls_b + cc);
    }
}

// ---------------- launch ----------------
extern "C" void kernel_launch(void* const* d_in, const int* in_sizes, int n_in,
                              void* d_out, int out_size) {
    const float* x      = (const float*)d_in[0];
    const void*  rowp   = d_in[1];
    const void*  colp   = d_in[2];
    const float* asg_W1 = (const float*)d_in[3];
    const float* asg_b1 = (const float*)d_in[4];
    const float* asg_W2 = (const float*)d_in[5];
    const float* asg_b2 = (const float*)d_in[6];
    const float* lin_W  = (const float*)d_in[7];
    const float* lin_b  = (const float*)d_in[8];
    const float* conv_W = (const float*)d_in[9];
    const float* bias   = (const float*)d_in[10];
    const float* cls_W  = (const float*)d_in[11];
    const float* cls_b  = (const float*)d_in[12];

    int N = in_sizes[0] / NFEAT;
    int E = in_sizes[1];
    int nb = (N + 255) / 256;

    float* hout   = (float*)d_out;
    float* logits = hout + (size_t)N * HIDDEN;

    cudaFuncSetAttribute(k_cmma, cudaFuncAttributeMaxDynamicSharedMemorySize,
                         SM_DYN);

    k_detect<<<1, 32>>>((const unsigned int*)rowp, E);
    k_fold<<<HIDDEN, NFEAT>>>(conv_W, lin_W, lin_b);
    k_proj<<<(N + 7) / 8, 256>>>(x, asg_W1, N);
    dim3 gg((N + 127) / 128, HIDDEN / 128);
    k_cmma<<<gg, 256, SM_DYN>>>(N);
    k_zero<<<(N + 255) / 256, 256>>>(N);
    k_hist<<<(E + 255) / 256, 256>>>(rowp, E);
    k_bsum<<<nb, 256>>>(N);
    k_bscan<<<1, 512>>>(nb);
    k_rows<<<nb, 256>>>(N);
    k_scatter<<<(E + 255) / 256, 256>>>(rowp, colp, asg_b1, asg_W2, asg_b2, E);
    k_agg<<<(N + 7) / 8, 256>>>(bias, cls_W, cls_b, hout, logits, N);
}